// round 6
// baseline (speedup 1.0000x reference)
#include <cuda_runtime.h>
#include <cstdint>
#include <math.h>

// Problem constants
#define BATCH 4
#define SEQ   2048
#define DMODEL 1024
#define NHEAD 16
#define HDIM  64
#define MROWS (BATCH * SEQ)   // 8192

// Scratch (allocation-free rule: __device__ globals)
__device__ float g_Q[(size_t)MROWS * DMODEL];
__device__ float g_K[(size_t)MROWS * DMODEL];
__device__ float g_V[(size_t)MROWS * DMODEL];
__device__ float g_C[(size_t)MROWS * DMODEL];

// ---------------------------------------------------------------------------
// Helpers: tf32 convert (round-to-nearest) and m16n8k8 tf32 MMA
// ---------------------------------------------------------------------------
__device__ __forceinline__ uint32_t f2tf(float x) {
    uint32_t r;
    asm("cvt.rna.tf32.f32 %0, %1;" : "=r"(r) : "f"(x));
    return r;
}
__device__ __forceinline__ void mma_tf32(float* c, const uint32_t* a, const uint32_t* b) {
    asm volatile(
        "mma.sync.aligned.m16n8k8.row.col.f32.tf32.tf32.f32 "
        "{%0,%1,%2,%3}, {%4,%5,%6,%7}, {%8,%9}, {%0,%1,%2,%3};"
        : "+f"(c[0]), "+f"(c[1]), "+f"(c[2]), "+f"(c[3])
        : "r"(a[0]), "r"(a[1]), "r"(a[2]), "r"(a[3]), "r"(b[0]), "r"(b[1]));
}

// Fragment-layout smem ("frag8"): tile stored as [rowgroup][kk][64] where the
// 64-float block holds, at float index (4g+q)*2+{0,1} (XOR-swizzled by 4*kk):
//   ( M[group*8+g][kk*8+q], M[group*8+g][kk*8+q+4] )
// Consumer fragment pair = one 64-bit LDS at (2*lane)^(4*kk). Conflict-free.

// ---------------------------------------------------------------------------
// GEMM: C[M,N] = A[M,K] @ W[N,K]^T + bias[N], tf32 mma.sync, frag8 smem.
// CTA tile 128x128, BK=32, 8 warps (4m x 2n), warp 32x64, double buffered.
// grid = (8, 64), block = 256.
// ---------------------------------------------------------------------------
#define GTILE 4096                      // u32 per 128x32 tile
#define GEMM_SMEM (4 * GTILE * 4)       // 65,536 B

__global__ __launch_bounds__(256, 2) void gemm_mma(
    const float* __restrict__ A,
    const float* __restrict__ W,
    const float* __restrict__ bias,
    float* __restrict__ C)
{
    extern __shared__ uint32_t smg[];
    // A buffers: smg + buf*GTILE ; W buffers: smg + 2*GTILE + buf*GTILE

    const int tid  = threadIdx.x;
    const int lane = tid & 31;
    const int wid  = tid >> 5;
    const int wm   = wid & 3;
    const int wn   = wid >> 2;
    const int g    = lane >> 2;
    const int q    = lane & 3;
    const int m0 = blockIdx.y * 128;
    const int n0 = blockIdx.x * 128;

    // producer indices: 2 threads per row, 16 k-values each
    const int pr = tid >> 1;      // row 0..127
    const int pt = tid & 1;       // k half
    const int pg = pr & 7;
    const int pgrp = pr >> 3;

    float acc[2][8][4];
    #pragma unroll
    for (int mf = 0; mf < 2; mf++)
        #pragma unroll
        for (int nf = 0; nf < 8; nf++)
            #pragma unroll
            for (int j = 0; j < 4; j++) acc[mf][nf][j] = 0.0f;

    float4 av[4], wv[4];

    // ---- load chunk 0 into regs ----
    #pragma unroll
    for (int i = 0; i < 4; i++) {
        int col = 16 * pt + 4 * i;
        av[i] = *(const float4*)(A + (size_t)(m0 + pr) * DMODEL + col);
        wv[i] = *(const float4*)(W + (size_t)(n0 + pr) * DMODEL + col);
    }
    // ---- store chunk 0 (frag8 layout) ----
    {
        uint32_t* An = smg;
        uint32_t* Wn = smg + 2 * GTILE;
        #pragma unroll
        for (int m = 0; m < 2; m++) {
            int kk = 2 * pt + m;
            uint32_t* ab = An + (pgrp * 4 + kk) * 64;
            uint32_t* wb = Wn + (pgrp * 4 + kk) * 64;
            uint4 f0 = make_uint4(f2tf(av[2*m].x), f2tf(av[2*m+1].x),
                                  f2tf(av[2*m].y), f2tf(av[2*m+1].y));
            uint4 f1 = make_uint4(f2tf(av[2*m].z), f2tf(av[2*m+1].z),
                                  f2tf(av[2*m].w), f2tf(av[2*m+1].w));
            *(uint4*)(ab + ((8*pg)     ^ (4*kk))) = f0;
            *(uint4*)(ab + ((8*pg + 4) ^ (4*kk))) = f1;
            uint4 h0 = make_uint4(f2tf(wv[2*m].x), f2tf(wv[2*m+1].x),
                                  f2tf(wv[2*m].y), f2tf(wv[2*m+1].y));
            uint4 h1 = make_uint4(f2tf(wv[2*m].z), f2tf(wv[2*m+1].z),
                                  f2tf(wv[2*m].w), f2tf(wv[2*m+1].w));
            *(uint4*)(wb + ((8*pg)     ^ (4*kk))) = h0;
            *(uint4*)(wb + ((8*pg + 4) ^ (4*kk))) = h1;
        }
    }
    __syncthreads();

    const int NCHUNK = DMODEL / 32;   // 32
    for (int c = 0; c < NCHUNK; c++) {
        if (c + 1 < NCHUNK) {
            int k0 = (c + 1) * 32;
            #pragma unroll
            for (int i = 0; i < 4; i++) {
                int col = k0 + 16 * pt + 4 * i;
                av[i] = *(const float4*)(A + (size_t)(m0 + pr) * DMODEL + col);
                wv[i] = *(const float4*)(W + (size_t)(n0 + pr) * DMODEL + col);
            }
        }

        const uint32_t* Ab = smg + (c & 1) * GTILE;
        const uint32_t* Wb = smg + 2 * GTILE + (c & 1) * GTILE;
        #pragma unroll
        for (int kk = 0; kk < 4; kk++) {
            const int fo = (2 * lane) ^ (4 * kk);
            uint32_t af[2][4];
            #pragma unroll
            for (int mf = 0; mf < 2; mf++) {
                const uint32_t* blk = Ab + ((4*wm + 2*mf) * 4 + kk) * 64;
                uint2 lo = *(const uint2*)(blk + fo);
                uint2 hi = *(const uint2*)(blk + 256 + fo);
                af[mf][0] = lo.x; af[mf][2] = lo.y;
                af[mf][1] = hi.x; af[mf][3] = hi.y;
            }
            #pragma unroll
            for (int nf = 0; nf < 8; nf++) {
                const uint32_t* wblk = Wb + ((8*wn + nf) * 4 + kk) * 64;
                uint2 bv = *(const uint2*)(wblk + fo);
                uint32_t bf[2] = {bv.x, bv.y};
                mma_tf32(acc[0][nf], af[0], bf);
                mma_tf32(acc[1][nf], af[1], bf);
            }
        }

        if (c + 1 < NCHUNK) {
            uint32_t* An = smg + ((c + 1) & 1) * GTILE;
            uint32_t* Wn = smg + 2 * GTILE + ((c + 1) & 1) * GTILE;
            #pragma unroll
            for (int m = 0; m < 2; m++) {
                int kk = 2 * pt + m;
                uint32_t* ab = An + (pgrp * 4 + kk) * 64;
                uint32_t* wb = Wn + (pgrp * 4 + kk) * 64;
                uint4 f0 = make_uint4(f2tf(av[2*m].x), f2tf(av[2*m+1].x),
                                      f2tf(av[2*m].y), f2tf(av[2*m+1].y));
                uint4 f1 = make_uint4(f2tf(av[2*m].z), f2tf(av[2*m+1].z),
                                      f2tf(av[2*m].w), f2tf(av[2*m+1].w));
                *(uint4*)(ab + ((8*pg)     ^ (4*kk))) = f0;
                *(uint4*)(ab + ((8*pg + 4) ^ (4*kk))) = f1;
                uint4 h0 = make_uint4(f2tf(wv[2*m].x), f2tf(wv[2*m+1].x),
                                      f2tf(wv[2*m].y), f2tf(wv[2*m+1].y));
                uint4 h1 = make_uint4(f2tf(wv[2*m].z), f2tf(wv[2*m+1].z),
                                      f2tf(wv[2*m].w), f2tf(wv[2*m+1].w));
                *(uint4*)(wb + ((8*pg)     ^ (4*kk))) = h0;
                *(uint4*)(wb + ((8*pg + 4) ^ (4*kk))) = h1;
            }
            __syncthreads();
        }
    }

    // Epilogue with bias
    #pragma unroll
    for (int mf = 0; mf < 2; mf++) {
        int row0 = m0 + wm * 32 + mf * 16 + g;
        #pragma unroll
        for (int nf = 0; nf < 8; nf++) {
            int col = n0 + wn * 64 + nf * 8 + 2 * q;
            float b0 = __ldg(bias + col);
            float b1 = __ldg(bias + col + 1);
            float2 v0 = make_float2(acc[mf][nf][0] + b0, acc[mf][nf][1] + b1);
            float2 v1 = make_float2(acc[mf][nf][2] + b0, acc[mf][nf][3] + b1);
            *(float2*)(C + (size_t)row0 * DMODEL + col) = v0;
            *(float2*)(C + (size_t)(row0 + 8) * DMODEL + col) = v1;
        }
    }
}

// ---------------------------------------------------------------------------
// Causal flash attention, tf32 mma.sync. Br = Bc = 64, 4 warps.
// Q,K in frag8 smem; V natural + XOR granule swizzle; P via shuffles.
// smem: Qfr 16KB + Kfr 16KB + Vs 16KB = 48KB. grid = (32, 64), block = 128.
// ---------------------------------------------------------------------------
#define ATTN_SMEM (12288 * 4)   // 49,152 B

__global__ __launch_bounds__(128, 4) void attn_mma(
    const float* __restrict__ Q,
    const float* __restrict__ K,
    const float* __restrict__ V,
    float* __restrict__ Cx)
{
    extern __shared__ uint32_t sma[];
    uint32_t* Qfr = sma;           // frag8: [8 grp][8 kk][64]
    uint32_t* Kfr = sma + 4096;    // frag8
    uint32_t* Vs  = sma + 8192;    // natural [key][dk], granule-swizzled

    const int tid  = threadIdx.x;
    const int lane = tid & 31;
    const int w    = tid >> 5;       // warp -> query rows [w*16, w*16+16)
    const int g    = lane >> 2;
    const int q    = lane & 3;
    const int qt   = gridDim.x - 1 - blockIdx.x;   // heavy tiles first
    const int bh   = blockIdx.y;
    const int b    = bh >> 4;
    const int h    = bh & 15;
    const int q0   = qt * 64;

    const int pr = tid >> 1;        // producer row (0..63)
    const int pt = tid & 1;
    const int pg = pr & 7;
    const int pgrp = pr >> 3;

    const size_t base = ((size_t)b * SEQ) * DMODEL + (size_t)h * HDIM;

    // ---- Load Q tile (scaled by 1/8) into frag8 smem ----
    {
        float4 av[8];
        const float* gq = Q + base + (size_t)(q0 + pr) * DMODEL + 32 * pt;
        #pragma unroll
        for (int i = 0; i < 8; i++) av[i] = *(const float4*)(gq + 4 * i);
        #pragma unroll
        for (int m = 0; m < 4; m++) {
            int kk = 4 * pt + m;
            uint32_t* blk = Qfr + (pgrp * 8 + kk) * 64;
            uint4 f0 = make_uint4(f2tf(av[2*m].x * 0.125f), f2tf(av[2*m+1].x * 0.125f),
                                  f2tf(av[2*m].y * 0.125f), f2tf(av[2*m+1].y * 0.125f));
            uint4 f1 = make_uint4(f2tf(av[2*m].z * 0.125f), f2tf(av[2*m+1].z * 0.125f),
                                  f2tf(av[2*m].w * 0.125f), f2tf(av[2*m+1].w * 0.125f));
            *(uint4*)(blk + ((8*pg)     ^ (4*kk))) = f0;
            *(uint4*)(blk + ((8*pg + 4) ^ (4*kk))) = f1;
        }
    }

    float o[8][4];
    #pragma unroll
    for (int nf = 0; nf < 8; nf++)
        #pragma unroll
        for (int j = 0; j < 4; j++) o[nf][j] = 0.0f;
    float mi0 = -1e30f, mi1 = -1e30f, li0 = 0.0f, li1 = 0.0f;

    for (int kt = 0; kt <= qt; kt++) {
        const int k0 = kt * 64;
        __syncthreads();   // prev iter consumed K/V; also orders Q store

        // ---- K tile -> frag8 ----
        {
            float4 av[8];
            const float* gk = K + base + (size_t)(k0 + pr) * DMODEL + 32 * pt;
            #pragma unroll
            for (int i = 0; i < 8; i++) av[i] = *(const float4*)(gk + 4 * i);
            #pragma unroll
            for (int m = 0; m < 4; m++) {
                int kk = 4 * pt + m;
                uint32_t* blk = Kfr + (pgrp * 8 + kk) * 64;
                uint4 f0 = make_uint4(f2tf(av[2*m].x), f2tf(av[2*m+1].x),
                                      f2tf(av[2*m].y), f2tf(av[2*m+1].y));
                uint4 f1 = make_uint4(f2tf(av[2*m].z), f2tf(av[2*m+1].z),
                                      f2tf(av[2*m].w), f2tf(av[2*m+1].w));
                *(uint4*)(blk + ((8*pg)     ^ (4*kk))) = f0;
                *(uint4*)(blk + ((8*pg + 4) ^ (4*kk))) = f1;
            }
        }
        // ---- V tile -> natural, granule-swizzled ----
        {
            const float* gv = V + base + (size_t)(k0 + pr) * DMODEL + 32 * pt;
            #pragma unroll
            for (int i = 0; i < 8; i++) {
                float4 vv = *(const float4*)(gv + 4 * i);
                int c4 = 8 * pt + i;
                uint4 tv = make_uint4(f2tf(vv.x), f2tf(vv.y), f2tf(vv.z), f2tf(vv.w));
                *(uint4*)(Vs + pr * 64 + 4 * (c4 ^ pg)) = tv;
            }
        }
        __syncthreads();

        // ---- S = Q @ K^T ----
        float s[8][4];
        #pragma unroll
        for (int nf = 0; nf < 8; nf++)
            #pragma unroll
            for (int j = 0; j < 4; j++) s[nf][j] = 0.0f;

        #pragma unroll
        for (int kk = 0; kk < 8; kk++) {
            const int fo = (2 * lane) ^ (4 * kk);
            const uint32_t* blkA = Qfr + (2 * w * 8 + kk) * 64;
            uint2 lo = *(const uint2*)(blkA + fo);
            uint2 hi = *(const uint2*)(blkA + 512 + fo);
            uint32_t af[4] = {lo.x, hi.x, lo.y, hi.y};
            #pragma unroll
            for (int nf = 0; nf < 8; nf++) {
                uint2 bv = *(const uint2*)(Kfr + (nf * 8 + kk) * 64 + fo);
                uint32_t bf[2] = {bv.x, bv.y};
                mma_tf32(s[nf], af, bf);
            }
        }

        // ---- causal mask on the diagonal tile ----
        if (kt == qt) {
            int row0 = q0 + w * 16 + g;
            int row1 = row0 + 8;
            #pragma unroll
            for (int nf = 0; nf < 8; nf++) {
                int c0 = k0 + nf * 8 + 2 * q;
                if (c0 > row0)     s[nf][0] = -1e30f;
                if (c0 + 1 > row0) s[nf][1] = -1e30f;
                if (c0 > row1)     s[nf][2] = -1e30f;
                if (c0 + 1 > row1) s[nf][3] = -1e30f;
            }
        }

        // ---- online softmax ----
        float mx0 = -1e30f, mx1 = -1e30f;
        #pragma unroll
        for (int nf = 0; nf < 8; nf++) {
            mx0 = fmaxf(mx0, fmaxf(s[nf][0], s[nf][1]));
            mx1 = fmaxf(mx1, fmaxf(s[nf][2], s[nf][3]));
        }
        mx0 = fmaxf(mx0, __shfl_xor_sync(0xffffffffu, mx0, 1));
        mx0 = fmaxf(mx0, __shfl_xor_sync(0xffffffffu, mx0, 2));
        mx1 = fmaxf(mx1, __shfl_xor_sync(0xffffffffu, mx1, 1));
        mx1 = fmaxf(mx1, __shfl_xor_sync(0xffffffffu, mx1, 2));
        float mn0 = fmaxf(mi0, mx0);
        float mn1 = fmaxf(mi1, mx1);

        float rs0 = 0.0f, rs1 = 0.0f;
        #pragma unroll
        for (int nf = 0; nf < 8; nf++) {
            s[nf][0] = __expf(s[nf][0] - mn0);
            s[nf][1] = __expf(s[nf][1] - mn0);
            s[nf][2] = __expf(s[nf][2] - mn1);
            s[nf][3] = __expf(s[nf][3] - mn1);
            rs0 += s[nf][0] + s[nf][1];
            rs1 += s[nf][2] + s[nf][3];
        }
        rs0 += __shfl_xor_sync(0xffffffffu, rs0, 1);
        rs0 += __shfl_xor_sync(0xffffffffu, rs0, 2);
        rs1 += __shfl_xor_sync(0xffffffffu, rs1, 1);
        rs1 += __shfl_xor_sync(0xffffffffu, rs1, 2);

        float al0 = __expf(mi0 - mn0);
        float al1 = __expf(mi1 - mn1);
        li0 = li0 * al0 + rs0;
        li1 = li1 * al1 + rs1;
        mi0 = mn0;
        mi1 = mn1;
        #pragma unroll
        for (int nf = 0; nf < 8; nf++) {
            o[nf][0] *= al0;
            o[nf][1] *= al0;
            o[nf][2] *= al1;
            o[nf][3] *= al1;
        }

        // ---- O += P @ V : A-frag of P via in-warp shuffles; B from Vs ----
        #pragma unroll
        for (int ks = 0; ks < 8; ks++) {
            int src0 = g * 4 + (q >> 1);
            int src1 = src0 + 2;
            float v0 = __shfl_sync(0xffffffffu, s[ks][0], src0);
            float v1 = __shfl_sync(0xffffffffu, s[ks][1], src0);
            float v2 = __shfl_sync(0xffffffffu, s[ks][2], src0);
            float v3 = __shfl_sync(0xffffffffu, s[ks][3], src0);
            float u0 = __shfl_sync(0xffffffffu, s[ks][0], src1);
            float u1 = __shfl_sync(0xffffffffu, s[ks][1], src1);
            float u2 = __shfl_sync(0xffffffffu, s[ks][2], src1);
            float u3 = __shfl_sync(0xffffffffu, s[ks][3], src1);
            bool r1 = (q & 1);
            uint32_t af[4];
            af[0] = f2tf(r1 ? v1 : v0);
            af[1] = f2tf(r1 ? v3 : v2);
            af[2] = f2tf(r1 ? u1 : u0);
            af[3] = f2tf(r1 ? u3 : u2);

            int rlo = ks * 8 + q;
            int rhi = rlo + 4;
            #pragma unroll
            for (int nf = 0; nf < 8; nf++) {
                int dk = nf * 8 + g;
                uint32_t bf[2];
                bf[0] = Vs[rlo * 64 + (dk ^ (q << 2))];
                bf[1] = Vs[rhi * 64 + (dk ^ ((q + 4) << 2))];
                mma_tf32(o[nf], af, bf);
            }
        }
    }

    // ---- epilogue: normalize and store ----
    float inv0 = 1.0f / li0;
    float inv1 = 1.0f / li1;
    int row0 = q0 + w * 16 + g;
    #pragma unroll
    for (int nf = 0; nf < 8; nf++) {
        int col = nf * 8 + 2 * q;
        float2 v0 = make_float2(o[nf][0] * inv0, o[nf][1] * inv0);
        float2 v1 = make_float2(o[nf][2] * inv1, o[nf][3] * inv1);
        *(float2*)(Cx + base + (size_t)row0 * DMODEL + col) = v0;
        *(float2*)(Cx + base + (size_t)(row0 + 8) * DMODEL + col) = v1;
    }
}

// ---------------------------------------------------------------------------
extern "C" void kernel_launch(void* const* d_in, const int* in_sizes, int n_in,
                              void* d_out, int out_size)
{
    const float* query = (const float*)d_in[0];
    const float* key   = (const float*)d_in[1];
    const float* value = (const float*)d_in[2];
    // d_in[3] = mask: constant causal tril; handled analytically.
    const float* wq = (const float*)d_in[4];
    const float* bq = (const float*)d_in[5];
    const float* wk = (const float*)d_in[6];
    const float* bk = (const float*)d_in[7];
    const float* wv = (const float*)d_in[8];
    const float* bv = (const float*)d_in[9];
    const float* wo = (const float*)d_in[10];
    const float* bo = (const float*)d_in[11];
    float* out = (float*)d_out;

    float *Q, *K, *V, *C;
    cudaGetSymbolAddress((void**)&Q, g_Q);
    cudaGetSymbolAddress((void**)&K, g_K);
    cudaGetSymbolAddress((void**)&V, g_V);
    cudaGetSymbolAddress((void**)&C, g_C);

    cudaFuncSetAttribute(gemm_mma,
                         cudaFuncAttributeMaxDynamicSharedMemorySize, GEMM_SMEM);
    cudaFuncSetAttribute(attn_mma,
                         cudaFuncAttributeMaxDynamicSharedMemorySize, ATTN_SMEM);

    dim3 gridG(DMODEL / 128, MROWS / 128);   // (8, 64)
    gemm_mma<<<gridG, 256, GEMM_SMEM>>>(query, wq, bq, Q);
    gemm_mma<<<gridG, 256, GEMM_SMEM>>>(key,   wk, bk, K);
    gemm_mma<<<gridG, 256, GEMM_SMEM>>>(value, wv, bv, V);

    dim3 gridA(SEQ / 64, BATCH * NHEAD);     // (32, 64)
    attn_mma<<<gridA, 128, ATTN_SMEM>>>(Q, K, V, C);

    gemm_mma<<<gridG, 256, GEMM_SMEM>>>(C, wo, bo, out);
}

// round 7
// speedup vs baseline: 1.5604x; 1.5604x over previous
#include <cuda_runtime.h>
#include <cstdint>
#include <math.h>

// Problem constants
#define BATCH 4
#define SEQ   2048
#define DMODEL 1024
#define NHEAD 16
#define HDIM  64
#define MROWS (BATCH * SEQ)   // 8192

// Scratch (allocation-free rule: __device__ globals)
__device__ float g_Q[(size_t)MROWS * DMODEL];
__device__ float g_K[(size_t)MROWS * DMODEL];
__device__ float g_V[(size_t)MROWS * DMODEL];
__device__ float g_C[(size_t)MROWS * DMODEL];

// ---------------------------------------------------------------------------
// Helpers
// ---------------------------------------------------------------------------
__device__ __forceinline__ uint32_t f2tf(float x) {
    uint32_t r;
    asm("cvt.rna.tf32.f32 %0, %1;" : "=r"(r) : "f"(x));
    return r;
}
__device__ __forceinline__ void mma_tf32(float* c, const uint32_t* a, const uint32_t* b) {
    asm volatile(
        "mma.sync.aligned.m16n8k8.row.col.f32.tf32.tf32.f32 "
        "{%0,%1,%2,%3}, {%4,%5,%6,%7}, {%8,%9}, {%0,%1,%2,%3};"
        : "+f"(c[0]), "+f"(c[1]), "+f"(c[2]), "+f"(c[3])
        : "r"(a[0]), "r"(a[1]), "r"(a[2]), "r"(a[3]), "r"(b[0]), "r"(b[1]));
}
__device__ __forceinline__ uint32_t sm_u32(const void* p) {
    return (uint32_t)__cvta_generic_to_shared(p);
}
// ldmatrix x4: four 8x8 b16 matrices == four 8x4 f32 blocks, fragment-ordered.
__device__ __forceinline__ void ldsm4(uint32_t addr, uint32_t& r0, uint32_t& r1,
                                      uint32_t& r2, uint32_t& r3) {
    asm volatile("ldmatrix.sync.aligned.m8n8.x4.shared.b16 {%0,%1,%2,%3}, [%4];"
                 : "=r"(r0), "=r"(r1), "=r"(r2), "=r"(r3) : "r"(addr));
}
// Per-lane ldmatrix address offsets (in elements), relative to tile origin:
//  A-side (x4 -> a0..a3 of one 16x8 A tile):
//    row = (lane&7) + 8*((lane>>3)&1), col = 4*(lane>>4)
//  B-side (x4 -> b0,b1 of nf and nf+1, two 8-col blocks = 16 rows):
//    row = 8*(lane>>4) + (lane&7),     col = 4*((lane>>3)&1)

// ---------------------------------------------------------------------------
// GEMM: C[M,N] = A[M,K] @ W[N,K]^T + bias[N], tf32 mma.sync.
// CTA tile 128x128, BK=32, 8 warps (4m x 2n), warp 32x64, double buffered.
// Row-major padded smem (stride 36 floats), ldmatrix consumer loads.
// grid = (8, 64), block = 256.
// ---------------------------------------------------------------------------
#define GSTR 36
#define GTILE (128 * GSTR)
#define GEMM_SMEM (4 * GTILE * 4)   // 73,728 B

__global__ __launch_bounds__(256, 2) void gemm_mma(
    const float* __restrict__ A,
    const float* __restrict__ W,
    const float* __restrict__ bias,
    float* __restrict__ C)
{
    extern __shared__ __align__(16) uint32_t smg[];
    uint32_t* As = smg;                 // [2][GTILE]
    uint32_t* Ws = smg + 2 * GTILE;     // [2][GTILE]

    const int tid  = threadIdx.x;
    const int lane = tid & 31;
    const int wid  = tid >> 5;
    const int wm   = wid & 3;
    const int wn   = wid >> 2;
    const int g    = lane >> 2;
    const int q    = lane & 3;
    const int m0 = blockIdx.y * 128;
    const int n0 = blockIdx.x * 128;

    const int a_row = (lane & 7) + 8 * ((lane >> 3) & 1);
    const int a_col = 4 * (lane >> 4);
    const int b_row = 8 * (lane >> 4) + (lane & 7);
    const int b_col = 4 * ((lane >> 3) & 1);

    float acc[2][8][4];
    #pragma unroll
    for (int mf = 0; mf < 2; mf++)
        #pragma unroll
        for (int nf = 0; nf < 8; nf++)
            #pragma unroll
            for (int j = 0; j < 4; j++) acc[mf][nf][j] = 0.0f;

    float4 av[4], wv[4];

    // ---- load chunk 0 ----
    #pragma unroll
    for (int i = 0; i < 4; i++) {
        int idx = tid + i * 256;
        int r = idx >> 3, c4 = idx & 7;
        av[i] = *(const float4*)(A + (size_t)(m0 + r) * DMODEL + c4 * 4);
        wv[i] = *(const float4*)(W + (size_t)(n0 + r) * DMODEL + c4 * 4);
    }
    #pragma unroll
    for (int i = 0; i < 4; i++) {
        int idx = tid + i * 256;
        int r = idx >> 3, c4 = idx & 7;
        uint4 ta = make_uint4(f2tf(av[i].x), f2tf(av[i].y), f2tf(av[i].z), f2tf(av[i].w));
        uint4 tw = make_uint4(f2tf(wv[i].x), f2tf(wv[i].y), f2tf(wv[i].z), f2tf(wv[i].w));
        *(uint4*)&As[r * GSTR + c4 * 4] = ta;
        *(uint4*)&Ws[r * GSTR + c4 * 4] = tw;
    }
    __syncthreads();

    const int NCHUNK = DMODEL / 32;   // 32
    for (int c = 0; c < NCHUNK; c++) {
        if (c + 1 < NCHUNK) {
            int k0 = (c + 1) * 32;
            #pragma unroll
            for (int i = 0; i < 4; i++) {
                int idx = tid + i * 256;
                int r = idx >> 3, c4 = idx & 7;
                av[i] = *(const float4*)(A + (size_t)(m0 + r) * DMODEL + k0 + c4 * 4);
                wv[i] = *(const float4*)(W + (size_t)(n0 + r) * DMODEL + k0 + c4 * 4);
            }
        }

        const uint32_t* Ab = As + (c & 1) * GTILE;
        const uint32_t* Wb = Ws + (c & 1) * GTILE;
        const uint32_t aA0 = sm_u32(Ab + (wm * 32 + a_row) * GSTR + a_col);
        const uint32_t aA1 = sm_u32(Ab + (wm * 32 + 16 + a_row) * GSTR + a_col);
        const uint32_t aB  = sm_u32(Wb + (wn * 64 + b_row) * GSTR + b_col);

        #pragma unroll
        for (int kk = 0; kk < 4; kk++) {
            uint32_t af0[4], af1[4];
            ldsm4(aA0 + kk * 32, af0[0], af0[1], af0[2], af0[3]);
            ldsm4(aA1 + kk * 32, af1[0], af1[1], af1[2], af1[3]);
            #pragma unroll
            for (int p = 0; p < 4; p++) {
                uint32_t b0, b1, b2, b3;
                ldsm4(aB + (p * 16 * GSTR) * 4 + kk * 32, b0, b1, b2, b3);
                uint32_t bf0[2] = {b0, b1};
                uint32_t bf1[2] = {b2, b3};
                mma_tf32(acc[0][2*p],     af0, bf0);
                mma_tf32(acc[1][2*p],     af1, bf0);
                mma_tf32(acc[0][2*p + 1], af0, bf1);
                mma_tf32(acc[1][2*p + 1], af1, bf1);
            }
        }

        if (c + 1 < NCHUNK) {
            uint32_t* An = As + ((c + 1) & 1) * GTILE;
            uint32_t* Wn = Ws + ((c + 1) & 1) * GTILE;
            #pragma unroll
            for (int i = 0; i < 4; i++) {
                int idx = tid + i * 256;
                int r = idx >> 3, c4 = idx & 7;
                uint4 ta = make_uint4(f2tf(av[i].x), f2tf(av[i].y), f2tf(av[i].z), f2tf(av[i].w));
                uint4 tw = make_uint4(f2tf(wv[i].x), f2tf(wv[i].y), f2tf(wv[i].z), f2tf(wv[i].w));
                *(uint4*)&An[r * GSTR + c4 * 4] = ta;
                *(uint4*)&Wn[r * GSTR + c4 * 4] = tw;
            }
            __syncthreads();
        }
    }

    // Epilogue with bias
    #pragma unroll
    for (int mf = 0; mf < 2; mf++) {
        int row0 = m0 + wm * 32 + mf * 16 + g;
        #pragma unroll
        for (int nf = 0; nf < 8; nf++) {
            int col = n0 + wn * 64 + nf * 8 + 2 * q;
            float b0 = __ldg(bias + col);
            float b1 = __ldg(bias + col + 1);
            float2 v0 = make_float2(acc[mf][nf][0] + b0, acc[mf][nf][1] + b1);
            float2 v1 = make_float2(acc[mf][nf][2] + b0, acc[mf][nf][3] + b1);
            *(float2*)(C + (size_t)row0 * DMODEL + col) = v0;
            *(float2*)(C + (size_t)(row0 + 8) * DMODEL + col) = v1;
        }
    }
}

// ---------------------------------------------------------------------------
// Causal flash attention via tf32 mma.sync. Br = Bc = 64, DK = 64.
// Block = 128 threads (4 warps), each warp owns 16 query rows.
// Round-4 layouts (stride 68), ldmatrix consumer loads.
// ---------------------------------------------------------------------------
#define ASTR 68
#define ATILE (64 * ASTR)
#define ATTN_SMEM (4 * ATILE * 4)    // 69,632 B

__global__ __launch_bounds__(128) void attn_mma(
    const float* __restrict__ Q,
    const float* __restrict__ K,
    const float* __restrict__ V,
    float* __restrict__ Cx)
{
    extern __shared__ __align__(16) uint32_t sma[];
    uint32_t* Qs = sma;              // [qrow][dk]
    uint32_t* Ks = sma + ATILE;      // [key][dk]
    uint32_t* Vt = sma + 2 * ATILE;  // [dk][key]
    uint32_t* Ps = sma + 3 * ATILE;  // [qrow][key]

    const int tid  = threadIdx.x;
    const int lane = tid & 31;
    const int w    = tid >> 5;
    const int g    = lane >> 2;
    const int q    = lane & 3;
    const int qt   = blockIdx.x;
    const int bh   = blockIdx.y;
    const int b    = bh >> 4;
    const int h    = bh & 15;
    const int q0   = qt * 64;

    const int a_row = (lane & 7) + 8 * ((lane >> 3) & 1);
    const int a_col = 4 * (lane >> 4);
    const int b_row = 8 * (lane >> 4) + (lane & 7);
    const int b_col = 4 * ((lane >> 3) & 1);

    const size_t base = ((size_t)b * SEQ) * DMODEL + (size_t)h * HDIM;

    // Load Q tile (scaled by 1/sqrt(dk), tf32-rounded)
    #pragma unroll
    for (int i = 0; i < 8; i++) {
        int idx = tid + i * 128;
        int r = idx >> 4, c4 = idx & 15;
        float4 v = *(const float4*)(Q + base + (size_t)(q0 + r) * DMODEL + c4 * 4);
        uint4 t = make_uint4(f2tf(v.x * 0.125f), f2tf(v.y * 0.125f),
                             f2tf(v.z * 0.125f), f2tf(v.w * 0.125f));
        *(uint4*)&Qs[r * ASTR + c4 * 4] = t;
    }

    const uint32_t aQ = sm_u32(Qs + (w * 16 + a_row) * ASTR + a_col);
    const uint32_t aK = sm_u32(Ks + b_row * ASTR + b_col);
    const uint32_t aP = sm_u32(Ps + (w * 16 + a_row) * ASTR + a_col);
    const uint32_t aV = sm_u32(Vt + b_row * ASTR + b_col);

    float o[8][4];
    #pragma unroll
    for (int nf = 0; nf < 8; nf++)
        #pragma unroll
        for (int j = 0; j < 4; j++) o[nf][j] = 0.0f;
    float mi0 = -1e30f, mi1 = -1e30f, li0 = 0.0f, li1 = 0.0f;

    for (int kt = 0; kt <= qt; kt++) {
        const int k0 = kt * 64;
        __syncthreads();   // previous iteration fully consumed Ks/Vt/Ps; Qs visible

        // Load K tile (natural [key][dk]) and V tile transposed -> Vt[dk][key]
        #pragma unroll
        for (int i = 0; i < 8; i++) {
            int idx = tid + i * 128;
            int r = idx >> 4, c4 = idx & 15;
            float4 kv = *(const float4*)(K + base + (size_t)(k0 + r) * DMODEL + c4 * 4);
            uint4 tk = make_uint4(f2tf(kv.x), f2tf(kv.y), f2tf(kv.z), f2tf(kv.w));
            *(uint4*)&Ks[r * ASTR + c4 * 4] = tk;
            float4 vv = *(const float4*)(V + base + (size_t)(k0 + r) * DMODEL + c4 * 4);
            Vt[(c4 * 4 + 0) * ASTR + r] = f2tf(vv.x);
            Vt[(c4 * 4 + 1) * ASTR + r] = f2tf(vv.y);
            Vt[(c4 * 4 + 2) * ASTR + r] = f2tf(vv.z);
            Vt[(c4 * 4 + 3) * ASTR + r] = f2tf(vv.w);
        }
        __syncthreads();

        // S = Q @ K^T (warp: 16 rows x 64 keys)
        float s[8][4];
        #pragma unroll
        for (int nf = 0; nf < 8; nf++)
            #pragma unroll
            for (int j = 0; j < 4; j++) s[nf][j] = 0.0f;

        #pragma unroll
        for (int kk = 0; kk < 8; kk++) {
            uint32_t af[4];
            ldsm4(aQ + kk * 32, af[0], af[1], af[2], af[3]);
            #pragma unroll
            for (int p = 0; p < 4; p++) {
                uint32_t b0, b1, b2, b3;
                ldsm4(aK + (p * 16 * ASTR) * 4 + kk * 32, b0, b1, b2, b3);
                uint32_t bf0[2] = {b0, b1};
                uint32_t bf1[2] = {b2, b3};
                mma_tf32(s[2*p],     af, bf0);
                mma_tf32(s[2*p + 1], af, bf1);
            }
        }

        // Causal mask on the diagonal tile
        if (kt == qt) {
            int row0 = q0 + w * 16 + g;
            int row1 = row0 + 8;
            #pragma unroll
            for (int nf = 0; nf < 8; nf++) {
                int c0 = k0 + nf * 8 + 2 * q;
                if (c0 > row0)     s[nf][0] = -1e30f;
                if (c0 + 1 > row0) s[nf][1] = -1e30f;
                if (c0 > row1)     s[nf][2] = -1e30f;
                if (c0 + 1 > row1) s[nf][3] = -1e30f;
            }
        }

        // Online softmax (rows g and g+8 owned by this lane's quad)
        float mx0 = -1e30f, mx1 = -1e30f;
        #pragma unroll
        for (int nf = 0; nf < 8; nf++) {
            mx0 = fmaxf(mx0, fmaxf(s[nf][0], s[nf][1]));
            mx1 = fmaxf(mx1, fmaxf(s[nf][2], s[nf][3]));
        }
        mx0 = fmaxf(mx0, __shfl_xor_sync(0xffffffffu, mx0, 1));
        mx0 = fmaxf(mx0, __shfl_xor_sync(0xffffffffu, mx0, 2));
        mx1 = fmaxf(mx1, __shfl_xor_sync(0xffffffffu, mx1, 1));
        mx1 = fmaxf(mx1, __shfl_xor_sync(0xffffffffu, mx1, 2));
        float mn0 = fmaxf(mi0, mx0);
        float mn1 = fmaxf(mi1, mx1);

        float rs0 = 0.0f, rs1 = 0.0f;
        #pragma unroll
        for (int nf = 0; nf < 8; nf++) {
            s[nf][0] = __expf(s[nf][0] - mn0);
            s[nf][1] = __expf(s[nf][1] - mn0);
            s[nf][2] = __expf(s[nf][2] - mn1);
            s[nf][3] = __expf(s[nf][3] - mn1);
            rs0 += s[nf][0] + s[nf][1];
            rs1 += s[nf][2] + s[nf][3];
        }
        rs0 += __shfl_xor_sync(0xffffffffu, rs0, 1);
        rs0 += __shfl_xor_sync(0xffffffffu, rs0, 2);
        rs1 += __shfl_xor_sync(0xffffffffu, rs1, 1);
        rs1 += __shfl_xor_sync(0xffffffffu, rs1, 2);

        float al0 = __expf(mi0 - mn0);
        float al1 = __expf(mi1 - mn1);
        li0 = li0 * al0 + rs0;
        li1 = li1 * al1 + rs1;
        mi0 = mn0;
        mi1 = mn1;
        #pragma unroll
        for (int nf = 0; nf < 8; nf++) {
            o[nf][0] *= al0;
            o[nf][1] *= al0;
            o[nf][2] *= al1;
            o[nf][3] *= al1;
        }

        // P -> smem (tf32), own 16 rows only
        #pragma unroll
        for (int nf = 0; nf < 8; nf++) {
            int r0 = w * 16 + g;
            int cc = nf * 8 + 2 * q;
            Ps[r0 * ASTR + cc]           = f2tf(s[nf][0]);
            Ps[r0 * ASTR + cc + 1]       = f2tf(s[nf][1]);
            Ps[(r0 + 8) * ASTR + cc]     = f2tf(s[nf][2]);
            Ps[(r0 + 8) * ASTR + cc + 1] = f2tf(s[nf][3]);
        }
        __syncwarp();

        // O += P @ V
        #pragma unroll
        for (int ks = 0; ks < 8; ks++) {
            uint32_t af[4];
            ldsm4(aP + ks * 32, af[0], af[1], af[2], af[3]);
            #pragma unroll
            for (int p = 0; p < 4; p++) {
                uint32_t b0, b1, b2, b3;
                ldsm4(aV + (p * 16 * ASTR) * 4 + ks * 32, b0, b1, b2, b3);
                uint32_t bf0[2] = {b0, b1};
                uint32_t bf1[2] = {b2, b3};
                mma_tf32(o[2*p],     af, bf0);
                mma_tf32(o[2*p + 1], af, bf1);
            }
        }
    }

    // Epilogue: normalize and store
    float inv0 = 1.0f / li0;
    float inv1 = 1.0f / li1;
    int row0 = q0 + w * 16 + g;
    #pragma unroll
    for (int nf = 0; nf < 8; nf++) {
        int col = nf * 8 + 2 * q;
        float2 v0 = make_float2(o[nf][0] * inv0, o[nf][1] * inv0);
        float2 v1 = make_float2(o[nf][2] * inv1, o[nf][3] * inv1);
        *(float2*)(Cx + base + (size_t)row0 * DMODEL + col) = v0;
        *(float2*)(Cx + base + (size_t)(row0 + 8) * DMODEL + col) = v1;
    }
}

// ---------------------------------------------------------------------------
extern "C" void kernel_launch(void* const* d_in, const int* in_sizes, int n_in,
                              void* d_out, int out_size)
{
    const float* query = (const float*)d_in[0];
    const float* key   = (const float*)d_in[1];
    const float* value = (const float*)d_in[2];
    // d_in[3] = mask: constant causal tril; handled analytically.
    const float* wq = (const float*)d_in[4];
    const float* bq = (const float*)d_in[5];
    const float* wk = (const float*)d_in[6];
    const float* bk = (const float*)d_in[7];
    const float* wv = (const float*)d_in[8];
    const float* bv = (const float*)d_in[9];
    const float* wo = (const float*)d_in[10];
    const float* bo = (const float*)d_in[11];
    float* out = (float*)d_out;

    float *Q, *K, *V, *C;
    cudaGetSymbolAddress((void**)&Q, g_Q);
    cudaGetSymbolAddress((void**)&K, g_K);
    cudaGetSymbolAddress((void**)&V, g_V);
    cudaGetSymbolAddress((void**)&C, g_C);

    cudaFuncSetAttribute(gemm_mma,
                         cudaFuncAttributeMaxDynamicSharedMemorySize, GEMM_SMEM);
    cudaFuncSetAttribute(attn_mma,
                         cudaFuncAttributeMaxDynamicSharedMemorySize, ATTN_SMEM);

    dim3 gridG(DMODEL / 128, MROWS / 128);   // (8, 64)
    gemm_mma<<<gridG, 256, GEMM_SMEM>>>(query, wq, bq, Q);
    gemm_mma<<<gridG, 256, GEMM_SMEM>>>(key,   wk, bk, K);
    gemm_mma<<<gridG, 256, GEMM_SMEM>>>(value, wv, bv, V);

    dim3 gridA(SEQ / 64, BATCH * NHEAD);     // (32, 64)
    attn_mma<<<gridA, 128, ATTN_SMEM>>>(Q, K, V, C);

    gemm_mma<<<gridG, 256, GEMM_SMEM>>>(C, wo, bo, out);
}

// round 8
// speedup vs baseline: 1.6897x; 1.0828x over previous
#include <cuda_runtime.h>
#include <cstdint>
#include <math.h>

// Problem constants
#define BATCH 4
#define SEQ   2048
#define DMODEL 1024
#define NHEAD 16
#define HDIM  64
#define MROWS (BATCH * SEQ)   // 8192

// Scratch (allocation-free rule: __device__ globals)
__device__ float g_Q[(size_t)MROWS * DMODEL];
__device__ float g_K[(size_t)MROWS * DMODEL];
__device__ float g_V[(size_t)MROWS * DMODEL];
__device__ float g_C[(size_t)MROWS * DMODEL];
__device__ float g_T[(size_t)MROWS * DMODEL];    // tf32-rounded activations
__device__ float g_Wr[(size_t)DMODEL * DMODEL];  // tf32-rounded weights

// ---------------------------------------------------------------------------
// Helpers
// ---------------------------------------------------------------------------
__device__ __forceinline__ uint32_t f2tf(float x) {
    uint32_t r;
    asm("cvt.rna.tf32.f32 %0, %1;" : "=r"(r) : "f"(x));
    return r;
}
__device__ __forceinline__ void mma_tf32(float* c, const uint32_t* a, const uint32_t* b) {
    asm volatile(
        "mma.sync.aligned.m16n8k8.row.col.f32.tf32.tf32.f32 "
        "{%0,%1,%2,%3}, {%4,%5,%6,%7}, {%8,%9}, {%0,%1,%2,%3};"
        : "+f"(c[0]), "+f"(c[1]), "+f"(c[2]), "+f"(c[3])
        : "r"(a[0]), "r"(a[1]), "r"(a[2]), "r"(a[3]), "r"(b[0]), "r"(b[1]));
}
__device__ __forceinline__ uint32_t sm_u32(const void* p) {
    return (uint32_t)__cvta_generic_to_shared(p);
}
__device__ __forceinline__ void ldsm4(uint32_t addr, uint32_t& r0, uint32_t& r1,
                                      uint32_t& r2, uint32_t& r3) {
    asm volatile("ldmatrix.sync.aligned.m8n8.x4.shared.b16 {%0,%1,%2,%3}, [%4];"
                 : "=r"(r0), "=r"(r1), "=r"(r2), "=r"(r3) : "r"(addr));
}
__device__ __forceinline__ void cp16(uint32_t saddr, const void* gaddr) {
    asm volatile("cp.async.cg.shared.global [%0], [%1], 16;"
                 :: "r"(saddr), "l"(gaddr));
}
__device__ __forceinline__ void cp_commit() {
    asm volatile("cp.async.commit_group;" ::: "memory");
}
template <int N>
__device__ __forceinline__ void cp_wait() {
    asm volatile("cp.async.wait_group %0;" :: "n"(N) : "memory");
}

// ---------------------------------------------------------------------------
// Round fp32 -> tf32 (round-to-nearest) elementwise.
// ---------------------------------------------------------------------------
__global__ void round_tf32_kernel(const float* __restrict__ in,
                                  float* __restrict__ out, int n4)
{
    int i = blockIdx.x * blockDim.x + threadIdx.x;
    if (i >= n4) return;
    float4 v = ((const float4*)in)[i];
    float4 o;
    o.x = __uint_as_float(f2tf(v.x));
    o.y = __uint_as_float(f2tf(v.y));
    o.z = __uint_as_float(f2tf(v.z));
    o.w = __uint_as_float(f2tf(v.w));
    ((float4*)out)[i] = o;
}

// ---------------------------------------------------------------------------
// GEMM: C[M,N] = A[M,K] @ W[N,K]^T + bias[N], tf32 mma.sync.
// Inputs pre-rounded to tf32. 3-stage cp.async pipeline, ldmatrix consumers.
// CTA tile 128x128, BK=32, 8 warps (4m x 2n). grid = (8, 64), block = 256.
// mode != 0: output = rna_tf32((acc + bias) * oscale); else plain fp32.
// ---------------------------------------------------------------------------
#define GSTR 36
#define GTILE (128 * GSTR)                    // u32 per tile
#define GSTAGE (2 * GTILE)                    // A + W
#define GEMM_SMEM (3 * GSTAGE * 4)            // 110,592 B

__global__ __launch_bounds__(256, 2) void gemm_mma(
    const float* __restrict__ A,
    const float* __restrict__ W,
    const float* __restrict__ bias,
    float* __restrict__ C,
    int mode, float oscale)
{
    extern __shared__ __align__(16) uint32_t smg[];

    const int tid  = threadIdx.x;
    const int lane = tid & 31;
    const int wid  = tid >> 5;
    const int wm   = wid & 3;
    const int wn   = wid >> 2;
    const int g    = lane >> 2;
    const int q    = lane & 3;
    const int m0 = blockIdx.y * 128;
    const int n0 = blockIdx.x * 128;

    const int a_row = (lane & 7) + 8 * ((lane >> 3) & 1);
    const int a_col = 4 * (lane >> 4);
    const int b_row = 8 * (lane >> 4) + (lane & 7);
    const int b_col = 4 * ((lane >> 3) & 1);

    float acc[2][8][4];
    #pragma unroll
    for (int mf = 0; mf < 2; mf++)
        #pragma unroll
        for (int nf = 0; nf < 8; nf++)
            #pragma unroll
            for (int j = 0; j < 4; j++) acc[mf][nf][j] = 0.0f;

    const uint32_t sbase = sm_u32(smg);
    // stage loader: 8 granules per thread (4 A + 4 W)
    auto load_stage = [&](int stage, int kc) {
        uint32_t ab = sbase + stage * (GSTAGE * 4);
        uint32_t wb = ab + GTILE * 4;
        #pragma unroll
        for (int i = 0; i < 4; i++) {
            int gi = tid + i * 256;
            int r = gi >> 3, c = gi & 7;
            cp16(ab + (r * GSTR + c * 4) * 4, A + (size_t)(m0 + r) * DMODEL + kc + c * 4);
            cp16(wb + (r * GSTR + c * 4) * 4, W + (size_t)(n0 + r) * DMODEL + kc + c * 4);
        }
        cp_commit();
    };

    load_stage(0, 0);
    load_stage(1, 32);

    const int NCHUNK = DMODEL / 32;   // 32
    for (int c = 0; c < NCHUNK; c++) {
        cp_wait<1>();
        __syncthreads();
        if (c + 2 < NCHUNK)
            load_stage((c + 2) % 3, (c + 2) * 32);

        const uint32_t* Sb = smg + (c % 3) * GSTAGE;
        const uint32_t aA0 = sm_u32(Sb + (wm * 32 + a_row) * GSTR + a_col);
        const uint32_t aA1 = aA0 + 16 * GSTR * 4;
        const uint32_t aB  = sm_u32(Sb + GTILE + (wn * 64 + b_row) * GSTR + b_col);

        #pragma unroll
        for (int kk = 0; kk < 4; kk++) {
            uint32_t af0[4], af1[4];
            ldsm4(aA0 + kk * 32, af0[0], af0[1], af0[2], af0[3]);
            ldsm4(aA1 + kk * 32, af1[0], af1[1], af1[2], af1[3]);
            #pragma unroll
            for (int p = 0; p < 4; p++) {
                uint32_t b0, b1, b2, b3;
                ldsm4(aB + (p * 16 * GSTR) * 4 + kk * 32, b0, b1, b2, b3);
                uint32_t bf0[2] = {b0, b1};
                uint32_t bf1[2] = {b2, b3};
                mma_tf32(acc[0][2*p],     af0, bf0);
                mma_tf32(acc[1][2*p],     af1, bf0);
                mma_tf32(acc[0][2*p + 1], af0, bf1);
                mma_tf32(acc[1][2*p + 1], af1, bf1);
            }
        }
        __syncthreads();
    }

    // Epilogue with bias (+ optional tf32 rounding / scaling)
    #pragma unroll
    for (int mf = 0; mf < 2; mf++) {
        int row0 = m0 + wm * 32 + mf * 16 + g;
        #pragma unroll
        for (int nf = 0; nf < 8; nf++) {
            int col = n0 + wn * 64 + nf * 8 + 2 * q;
            float b0 = __ldg(bias + col);
            float b1 = __ldg(bias + col + 1);
            float v00 = acc[mf][nf][0] + b0, v01 = acc[mf][nf][1] + b1;
            float v10 = acc[mf][nf][2] + b0, v11 = acc[mf][nf][3] + b1;
            if (mode) {
                v00 = __uint_as_float(f2tf(v00 * oscale));
                v01 = __uint_as_float(f2tf(v01 * oscale));
                v10 = __uint_as_float(f2tf(v10 * oscale));
                v11 = __uint_as_float(f2tf(v11 * oscale));
            }
            *(float2*)(C + (size_t)row0 * DMODEL + col) = make_float2(v00, v01);
            *(float2*)(C + (size_t)(row0 + 8) * DMODEL + col) = make_float2(v10, v11);
        }
    }
}

// ---------------------------------------------------------------------------
// Causal flash attention via tf32 mma.sync. Br = Bc = 64, 4 warps.
// Q/K/V pre-rounded (Q pre-scaled by 1/8). cp.async loads, double-buffered
// K/V, natural-layout V with scalar B-fragment loads (no transpose).
// smem: Qs + K0 + K1 + V0 + V1 + Ps = 6 x 17,408 B = 104,448 B.
// grid = (32, 64) heavy-first, block = 128.
// ---------------------------------------------------------------------------
#define ASTR 68
#define ATILE (64 * ASTR)
#define ATTN_SMEM (6 * ATILE * 4)    // 104,448 B

__global__ __launch_bounds__(128) void attn_mma(
    const float* __restrict__ Q,
    const float* __restrict__ K,
    const float* __restrict__ V,
    float* __restrict__ Cx)
{
    extern __shared__ __align__(16) uint32_t sma[];
    uint32_t* Qs = sma;                       // [qrow][dk]
    uint32_t* Kb[2] = {sma + ATILE, sma + 2 * ATILE};
    uint32_t* Vb[2] = {sma + 3 * ATILE, sma + 4 * ATILE};
    uint32_t* Ps = sma + 5 * ATILE;           // [qrow][key]

    const int tid  = threadIdx.x;
    const int lane = tid & 31;
    const int w    = tid >> 5;
    const int g    = lane >> 2;
    const int q    = lane & 3;
    const int qt   = gridDim.x - 1 - blockIdx.x;   // heavy tiles first
    const int bh   = blockIdx.y;
    const int b    = bh >> 4;
    const int h    = bh & 15;
    const int q0   = qt * 64;

    const int a_row = (lane & 7) + 8 * ((lane >> 3) & 1);
    const int a_col = 4 * (lane >> 4);
    const int b_row = 8 * (lane >> 4) + (lane & 7);
    const int b_col = 4 * ((lane >> 3) & 1);

    const size_t base = ((size_t)b * SEQ) * DMODEL + (size_t)h * HDIM;

    // tile copy: 8 granules per thread (64 rows x 16 granules)
    auto load_tile = [&](uint32_t* dst, const float* src, int r0) {
        uint32_t db = sm_u32(dst);
        #pragma unroll
        for (int i = 0; i < 8; i++) {
            int gi = tid + i * 128;
            int r = gi >> 4, c = gi & 15;
            cp16(db + (r * ASTR + c * 4) * 4, src + base + (size_t)(r0 + r) * DMODEL + c * 4);
        }
    };

    // prologue: Q + (K,V) tile 0 in one group
    load_tile(Qs, Q, q0);
    load_tile(Kb[0], K, 0);
    load_tile(Vb[0], V, 0);
    cp_commit();

    const uint32_t aQ = sm_u32(Qs + (w * 16 + a_row) * ASTR + a_col);
    const uint32_t aP = sm_u32(Ps + (w * 16 + a_row) * ASTR + a_col);
    const uint32_t aK0 = sm_u32(Kb[0] + b_row * ASTR + b_col);
    const uint32_t aK1 = sm_u32(Kb[1] + b_row * ASTR + b_col);

    float o[8][4];
    #pragma unroll
    for (int nf = 0; nf < 8; nf++)
        #pragma unroll
        for (int j = 0; j < 4; j++) o[nf][j] = 0.0f;
    float mi0 = -1e30f, mi1 = -1e30f, li0 = 0.0f, li1 = 0.0f;

    for (int kt = 0; kt <= qt; kt++) {
        const int cur = kt & 1;
        cp_wait<0>();
        __syncthreads();   // cur tile visible; prev buffer fully consumed

        if (kt < qt) {
            load_tile(Kb[cur ^ 1], K, (kt + 1) * 64);
            load_tile(Vb[cur ^ 1], V, (kt + 1) * 64);
            cp_commit();
        }

        // ---- S = Q @ K^T ----
        float s[8][4];
        #pragma unroll
        for (int nf = 0; nf < 8; nf++)
            #pragma unroll
            for (int j = 0; j < 4; j++) s[nf][j] = 0.0f;

        const uint32_t aK = cur ? aK1 : aK0;
        #pragma unroll
        for (int kk = 0; kk < 8; kk++) {
            uint32_t af[4];
            ldsm4(aQ + kk * 32, af[0], af[1], af[2], af[3]);
            #pragma unroll
            for (int p = 0; p < 4; p++) {
                uint32_t b0, b1, b2, b3;
                ldsm4(aK + (p * 16 * ASTR) * 4 + kk * 32, b0, b1, b2, b3);
                uint32_t bf0[2] = {b0, b1};
                uint32_t bf1[2] = {b2, b3};
                mma_tf32(s[2*p],     af, bf0);
                mma_tf32(s[2*p + 1], af, bf1);
            }
        }

        // ---- causal mask on the diagonal tile ----
        if (kt == qt) {
            int row0 = q0 + w * 16 + g;
            int row1 = row0 + 8;
            int k0 = kt * 64;
            #pragma unroll
            for (int nf = 0; nf < 8; nf++) {
                int c0 = k0 + nf * 8 + 2 * q;
                if (c0 > row0)     s[nf][0] = -1e30f;
                if (c0 + 1 > row0) s[nf][1] = -1e30f;
                if (c0 > row1)     s[nf][2] = -1e30f;
                if (c0 + 1 > row1) s[nf][3] = -1e30f;
            }
        }

        // ---- online softmax ----
        float mx0 = -1e30f, mx1 = -1e30f;
        #pragma unroll
        for (int nf = 0; nf < 8; nf++) {
            mx0 = fmaxf(mx0, fmaxf(s[nf][0], s[nf][1]));
            mx1 = fmaxf(mx1, fmaxf(s[nf][2], s[nf][3]));
        }
        mx0 = fmaxf(mx0, __shfl_xor_sync(0xffffffffu, mx0, 1));
        mx0 = fmaxf(mx0, __shfl_xor_sync(0xffffffffu, mx0, 2));
        mx1 = fmaxf(mx1, __shfl_xor_sync(0xffffffffu, mx1, 1));
        mx1 = fmaxf(mx1, __shfl_xor_sync(0xffffffffu, mx1, 2));
        float mn0 = fmaxf(mi0, mx0);
        float mn1 = fmaxf(mi1, mx1);

        float rs0 = 0.0f, rs1 = 0.0f;
        #pragma unroll
        for (int nf = 0; nf < 8; nf++) {
            s[nf][0] = __expf(s[nf][0] - mn0);
            s[nf][1] = __expf(s[nf][1] - mn0);
            s[nf][2] = __expf(s[nf][2] - mn1);
            s[nf][3] = __expf(s[nf][3] - mn1);
            rs0 += s[nf][0] + s[nf][1];
            rs1 += s[nf][2] + s[nf][3];
        }
        rs0 += __shfl_xor_sync(0xffffffffu, rs0, 1);
        rs0 += __shfl_xor_sync(0xffffffffu, rs0, 2);
        rs1 += __shfl_xor_sync(0xffffffffu, rs1, 1);
        rs1 += __shfl_xor_sync(0xffffffffu, rs1, 2);

        float al0 = __expf(mi0 - mn0);
        float al1 = __expf(mi1 - mn1);
        li0 = li0 * al0 + rs0;
        li1 = li1 * al1 + rs1;
        mi0 = mn0;
        mi1 = mn1;
        #pragma unroll
        for (int nf = 0; nf < 8; nf++) {
            o[nf][0] *= al0;
            o[nf][1] *= al0;
            o[nf][2] *= al1;
            o[nf][3] *= al1;
        }

        // ---- P -> smem (tf32), own 16 rows only ----
        #pragma unroll
        for (int nf = 0; nf < 8; nf++) {
            int r0 = w * 16 + g;
            int cc = nf * 8 + 2 * q;
            Ps[r0 * ASTR + cc]           = f2tf(s[nf][0]);
            Ps[r0 * ASTR + cc + 1]       = f2tf(s[nf][1]);
            Ps[(r0 + 8) * ASTR + cc]     = f2tf(s[nf][2]);
            Ps[(r0 + 8) * ASTR + cc + 1] = f2tf(s[nf][3]);
        }
        __syncwarp();

        // ---- O += P @ V : A via ldmatrix on Ps, B via scalar LDS on natural V ----
        const uint32_t* vb = Vb[cur] + q * ASTR + g;
        #pragma unroll
        for (int ks = 0; ks < 8; ks++) {
            uint32_t af[4];
            ldsm4(aP + ks * 32, af[0], af[1], af[2], af[3]);
            const uint32_t* vk = vb + ks * 8 * ASTR;
            #pragma unroll
            for (int p = 0; p < 4; p++) {
                uint32_t bf0[2] = { vk[16 * p],     vk[4 * ASTR + 16 * p] };
                uint32_t bf1[2] = { vk[16 * p + 8], vk[4 * ASTR + 16 * p + 8] };
                mma_tf32(o[2*p],     af, bf0);
                mma_tf32(o[2*p + 1], af, bf1);
            }
        }
    }

    // ---- epilogue: normalize, round to tf32 (input of O-proj), store ----
    float inv0 = 1.0f / li0;
    float inv1 = 1.0f / li1;
    int row0 = q0 + w * 16 + g;
    #pragma unroll
    for (int nf = 0; nf < 8; nf++) {
        int col = nf * 8 + 2 * q;
        float2 v0 = make_float2(__uint_as_float(f2tf(o[nf][0] * inv0)),
                                __uint_as_float(f2tf(o[nf][1] * inv0)));
        float2 v1 = make_float2(__uint_as_float(f2tf(o[nf][2] * inv1)),
                                __uint_as_float(f2tf(o[nf][3] * inv1)));
        *(float2*)(Cx + base + (size_t)row0 * DMODEL + col) = v0;
        *(float2*)(Cx + base + (size_t)(row0 + 8) * DMODEL + col) = v1;
    }
}

// ---------------------------------------------------------------------------
extern "C" void kernel_launch(void* const* d_in, const int* in_sizes, int n_in,
                              void* d_out, int out_size)
{
    const float* query = (const float*)d_in[0];
    const float* key   = (const float*)d_in[1];
    const float* value = (const float*)d_in[2];
    // d_in[3] = mask: constant causal tril; handled analytically.
    const float* wq = (const float*)d_in[4];
    const float* bq = (const float*)d_in[5];
    const float* wk = (const float*)d_in[6];
    const float* bk = (const float*)d_in[7];
    const float* wv = (const float*)d_in[8];
    const float* bv = (const float*)d_in[9];
    const float* wo = (const float*)d_in[10];
    const float* bo = (const float*)d_in[11];
    float* out = (float*)d_out;

    float *Q, *K, *V, *C, *T, *Wr;
    cudaGetSymbolAddress((void**)&Q,  g_Q);
    cudaGetSymbolAddress((void**)&K,  g_K);
    cudaGetSymbolAddress((void**)&V,  g_V);
    cudaGetSymbolAddress((void**)&C,  g_C);
    cudaGetSymbolAddress((void**)&T,  g_T);
    cudaGetSymbolAddress((void**)&Wr, g_Wr);

    cudaFuncSetAttribute(gemm_mma,
                         cudaFuncAttributeMaxDynamicSharedMemorySize, GEMM_SMEM);
    cudaFuncSetAttribute(attn_mma,
                         cudaFuncAttributeMaxDynamicSharedMemorySize, ATTN_SMEM);

    const int nact4 = MROWS * DMODEL / 4;   // 2,097,152
    const int nw4   = DMODEL * DMODEL / 4;  // 262,144
    dim3 gridG(DMODEL / 128, MROWS / 128);  // (8, 64)

    // Q projection (output pre-scaled by 1/sqrt(dk) and tf32-rounded)
    round_tf32_kernel<<<(nact4 + 255) / 256, 256>>>(query, T, nact4);
    round_tf32_kernel<<<(nw4 + 255) / 256, 256>>>(wq, Wr, nw4);
    gemm_mma<<<gridG, 256, GEMM_SMEM>>>(T, Wr, bq, Q, 1, 0.125f);

    // K projection
    round_tf32_kernel<<<(nact4 + 255) / 256, 256>>>(key, T, nact4);
    round_tf32_kernel<<<(nw4 + 255) / 256, 256>>>(wk, Wr, nw4);
    gemm_mma<<<gridG, 256, GEMM_SMEM>>>(T, Wr, bk, K, 1, 1.0f);

    // V projection
    round_tf32_kernel<<<(nact4 + 255) / 256, 256>>>(value, T, nact4);
    round_tf32_kernel<<<(nw4 + 255) / 256, 256>>>(wv, Wr, nw4);
    gemm_mma<<<gridG, 256, GEMM_SMEM>>>(T, Wr, bv, V, 1, 1.0f);

    // Attention (writes tf32-rounded C)
    dim3 gridA(SEQ / 64, BATCH * NHEAD);    // (32, 64)
    attn_mma<<<gridA, 128, ATTN_SMEM>>>(Q, K, V, C);

    // Output projection (plain fp32 output)
    round_tf32_kernel<<<(nw4 + 255) / 256, 256>>>(wo, Wr, nw4);
    gemm_mma<<<gridG, 256, GEMM_SMEM>>>(C, Wr, bo, out, 0, 1.0f);
}

// round 9
// speedup vs baseline: 1.8243x; 1.0797x over previous
#include <cuda_runtime.h>
#include <cstdint>
#include <math.h>

// Problem constants
#define BATCH 4
#define SEQ   2048
#define DMODEL 1024
#define NHEAD 16
#define HDIM  64
#define MROWS (BATCH * SEQ)   // 8192

// Scratch (allocation-free rule: __device__ globals)
__device__ float g_Q[(size_t)MROWS * DMODEL];
__device__ float g_K[(size_t)MROWS * DMODEL];
__device__ float g_V[(size_t)MROWS * DMODEL];
__device__ float g_C[(size_t)MROWS * DMODEL];
__device__ float g_T[3][(size_t)MROWS * DMODEL];   // tf32-rounded activations
__device__ float g_Wr[4][(size_t)DMODEL * DMODEL]; // tf32-rounded weights

// ---------------------------------------------------------------------------
// Helpers
// ---------------------------------------------------------------------------
__device__ __forceinline__ uint32_t f2tf(float x) {
    uint32_t r;
    asm("cvt.rna.tf32.f32 %0, %1;" : "=r"(r) : "f"(x));
    return r;
}
__device__ __forceinline__ void mma_tf32(float* c, const uint32_t* a, const uint32_t* b) {
    asm volatile(
        "mma.sync.aligned.m16n8k8.row.col.f32.tf32.tf32.f32 "
        "{%0,%1,%2,%3}, {%4,%5,%6,%7}, {%8,%9}, {%0,%1,%2,%3};"
        : "+f"(c[0]), "+f"(c[1]), "+f"(c[2]), "+f"(c[3])
        : "r"(a[0]), "r"(a[1]), "r"(a[2]), "r"(a[3]), "r"(b[0]), "r"(b[1]));
}
__device__ __forceinline__ uint32_t sm_u32(const void* p) {
    return (uint32_t)__cvta_generic_to_shared(p);
}
__device__ __forceinline__ void ldsm4(uint32_t addr, uint32_t& r0, uint32_t& r1,
                                      uint32_t& r2, uint32_t& r3) {
    asm volatile("ldmatrix.sync.aligned.m8n8.x4.shared.b16 {%0,%1,%2,%3}, [%4];"
                 : "=r"(r0), "=r"(r1), "=r"(r2), "=r"(r3) : "r"(addr));
}
__device__ __forceinline__ void cp16(uint32_t saddr, const void* gaddr) {
    asm volatile("cp.async.cg.shared.global [%0], [%1], 16;"
                 :: "r"(saddr), "l"(gaddr));
}
__device__ __forceinline__ void cp_commit() {
    asm volatile("cp.async.commit_group;" ::: "memory");
}
template <int N>
__device__ __forceinline__ void cp_wait() {
    asm volatile("cp.async.wait_group %0;" :: "n"(N) : "memory");
}

// ---------------------------------------------------------------------------
// Batched tf32 rounding (round-to-nearest).
// ---------------------------------------------------------------------------
struct Round3Args { const float *i0, *i1, *i2; float *o0, *o1, *o2; };
__global__ void round3_kernel(Round3Args a, int n4)
{
    int i = blockIdx.x * blockDim.x + threadIdx.x;
    if (i >= n4) return;
    const float* in = (blockIdx.y == 0) ? a.i0 : (blockIdx.y == 1) ? a.i1 : a.i2;
    float* out      = (blockIdx.y == 0) ? a.o0 : (blockIdx.y == 1) ? a.o1 : a.o2;
    float4 v = ((const float4*)in)[i];
    float4 o;
    o.x = __uint_as_float(f2tf(v.x));
    o.y = __uint_as_float(f2tf(v.y));
    o.z = __uint_as_float(f2tf(v.z));
    o.w = __uint_as_float(f2tf(v.w));
    ((float4*)out)[i] = o;
}
struct Round4Args { const float *i0, *i1, *i2, *i3; float *o0, *o1, *o2, *o3; };
__global__ void round4_kernel(Round4Args a, int n4)
{
    int i = blockIdx.x * blockDim.x + threadIdx.x;
    if (i >= n4) return;
    const float* in;
    float* out;
    switch (blockIdx.y) {
        case 0: in = a.i0; out = a.o0; break;
        case 1: in = a.i1; out = a.o1; break;
        case 2: in = a.i2; out = a.o2; break;
        default: in = a.i3; out = a.o3; break;
    }
    float4 v = ((const float4*)in)[i];
    float4 o;
    o.x = __uint_as_float(f2tf(v.x));
    o.y = __uint_as_float(f2tf(v.y));
    o.z = __uint_as_float(f2tf(v.z));
    o.w = __uint_as_float(f2tf(v.w));
    ((float4*)out)[i] = o;
}

// ---------------------------------------------------------------------------
// GEMM core: C[M,N] = A[M,K] @ W[N,K]^T + bias[N], tf32 mma.sync.
// Pre-rounded inputs. 3-stage cp.async pipeline, ldmatrix consumers.
// CTA tile 128x128, BK=32, 8 warps. block = 256.
// mode != 0: out = rna_tf32((acc + bias) * oscale); else plain fp32.
// ---------------------------------------------------------------------------
#define GSTR 36
#define GTILE (128 * GSTR)
#define GSTAGE (2 * GTILE)
#define GEMM_SMEM (3 * GSTAGE * 4)   // 110,592 B

__device__ __forceinline__ void gemm_body(
    const float* __restrict__ A, const float* __restrict__ W,
    const float* __restrict__ bias, float* __restrict__ C,
    int mode, float oscale, uint32_t* smg, int m0, int n0)
{
    const int tid  = threadIdx.x;
    const int lane = tid & 31;
    const int wid  = tid >> 5;
    const int wm   = wid & 3;
    const int wn   = wid >> 2;
    const int g    = lane >> 2;
    const int q    = lane & 3;

    const int a_row = (lane & 7) + 8 * ((lane >> 3) & 1);
    const int a_col = 4 * (lane >> 4);
    const int b_row = 8 * (lane >> 4) + (lane & 7);
    const int b_col = 4 * ((lane >> 3) & 1);

    float acc[2][8][4];
    #pragma unroll
    for (int mf = 0; mf < 2; mf++)
        #pragma unroll
        for (int nf = 0; nf < 8; nf++)
            #pragma unroll
            for (int j = 0; j < 4; j++) acc[mf][nf][j] = 0.0f;

    const uint32_t sbase = sm_u32(smg);
    auto load_stage = [&](int stage, int kc) {
        uint32_t ab = sbase + stage * (GSTAGE * 4);
        uint32_t wb = ab + GTILE * 4;
        #pragma unroll
        for (int i = 0; i < 4; i++) {
            int gi = tid + i * 256;
            int r = gi >> 3, c = gi & 7;
            cp16(ab + (r * GSTR + c * 4) * 4, A + (size_t)(m0 + r) * DMODEL + kc + c * 4);
            cp16(wb + (r * GSTR + c * 4) * 4, W + (size_t)(n0 + r) * DMODEL + kc + c * 4);
        }
        cp_commit();
    };

    load_stage(0, 0);
    load_stage(1, 32);

    const int NCHUNK = DMODEL / 32;
    for (int c = 0; c < NCHUNK; c++) {
        cp_wait<1>();
        __syncthreads();
        if (c + 2 < NCHUNK)
            load_stage((c + 2) % 3, (c + 2) * 32);

        const uint32_t* Sb = smg + (c % 3) * GSTAGE;
        const uint32_t aA0 = sm_u32(Sb + (wm * 32 + a_row) * GSTR + a_col);
        const uint32_t aA1 = aA0 + 16 * GSTR * 4;
        const uint32_t aB  = sm_u32(Sb + GTILE + (wn * 64 + b_row) * GSTR + b_col);

        #pragma unroll
        for (int kk = 0; kk < 4; kk++) {
            uint32_t af0[4], af1[4];
            ldsm4(aA0 + kk * 32, af0[0], af0[1], af0[2], af0[3]);
            ldsm4(aA1 + kk * 32, af1[0], af1[1], af1[2], af1[3]);
            #pragma unroll
            for (int p = 0; p < 4; p++) {
                uint32_t b0, b1, b2, b3;
                ldsm4(aB + (p * 16 * GSTR) * 4 + kk * 32, b0, b1, b2, b3);
                uint32_t bf0[2] = {b0, b1};
                uint32_t bf1[2] = {b2, b3};
                mma_tf32(acc[0][2*p],     af0, bf0);
                mma_tf32(acc[1][2*p],     af1, bf0);
                mma_tf32(acc[0][2*p + 1], af0, bf1);
                mma_tf32(acc[1][2*p + 1], af1, bf1);
            }
        }
        __syncthreads();
    }

    #pragma unroll
    for (int mf = 0; mf < 2; mf++) {
        int row0 = m0 + wm * 32 + mf * 16 + g;
        #pragma unroll
        for (int nf = 0; nf < 8; nf++) {
            int col = n0 + wn * 64 + nf * 8 + 2 * q;
            float b0 = __ldg(bias + col);
            float b1 = __ldg(bias + col + 1);
            float v00 = acc[mf][nf][0] + b0, v01 = acc[mf][nf][1] + b1;
            float v10 = acc[mf][nf][2] + b0, v11 = acc[mf][nf][3] + b1;
            if (mode) {
                v00 = __uint_as_float(f2tf(v00 * oscale));
                v01 = __uint_as_float(f2tf(v01 * oscale));
                v10 = __uint_as_float(f2tf(v10 * oscale));
                v11 = __uint_as_float(f2tf(v11 * oscale));
            }
            *(float2*)(C + (size_t)row0 * DMODEL + col) = make_float2(v00, v01);
            *(float2*)(C + (size_t)(row0 + 8) * DMODEL + col) = make_float2(v10, v11);
        }
    }
}

// Single GEMM (output projection)
__global__ __launch_bounds__(256, 2) void gemm_mma(
    const float* __restrict__ A, const float* __restrict__ W,
    const float* __restrict__ bias, float* __restrict__ C,
    int mode, float oscale)
{
    extern __shared__ __align__(16) uint32_t smg[];
    gemm_body(A, W, bias, C, mode, oscale, smg, blockIdx.y * 128, blockIdx.x * 128);
}

// Fused Q/K/V projections: blockIdx.z selects stream (z=0 Q with 0.125 scale).
struct QKVArgs {
    const float *A0, *A1, *A2;
    const float *W0, *W1, *W2;
    const float *b0, *b1, *b2;
    float *O0, *O1, *O2;
};
__global__ __launch_bounds__(256, 2) void gemm_qkv(QKVArgs a)
{
    extern __shared__ __align__(16) uint32_t smg[];
    const int z = blockIdx.z;
    const float* A = (z == 0) ? a.A0 : (z == 1) ? a.A1 : a.A2;
    const float* W = (z == 0) ? a.W0 : (z == 1) ? a.W1 : a.W2;
    const float* b = (z == 0) ? a.b0 : (z == 1) ? a.b1 : a.b2;
    float* O       = (z == 0) ? a.O0 : (z == 1) ? a.O1 : a.O2;
    float oscale   = (z == 0) ? 0.125f : 1.0f;
    gemm_body(A, W, b, O, 1, oscale, smg, blockIdx.y * 128, blockIdx.x * 128);
}

// ---------------------------------------------------------------------------
// Causal flash attention via tf32 mma.sync. Br = Bc = 64, 4 warps.
// Q/K/V pre-rounded (Q pre-scaled by 1/8). Single-buffered K and V with
// cp.async group-order pipelining. smem = 4 tiles = 69,632 B -> 3 CTAs/SM.
// grid = (32, 64) heavy-first, block = 128.
// ---------------------------------------------------------------------------
#define ASTR 68
#define ATILE (64 * ASTR)
#define ATTN_SMEM (4 * ATILE * 4)    // 69,632 B

__global__ __launch_bounds__(128) void attn_mma(
    const float* __restrict__ Q,
    const float* __restrict__ K,
    const float* __restrict__ V,
    float* __restrict__ Cx)
{
    extern __shared__ __align__(16) uint32_t sma[];
    uint32_t* Qs = sma;                // [qrow][dk]
    uint32_t* Ks = sma + ATILE;        // [key][dk]
    uint32_t* Vs = sma + 2 * ATILE;    // [key][dk] natural
    uint32_t* Ps = sma + 3 * ATILE;    // [qrow][key]

    const int tid  = threadIdx.x;
    const int lane = tid & 31;
    const int w    = tid >> 5;
    const int g    = lane >> 2;
    const int q    = lane & 3;
    const int qt   = gridDim.x - 1 - blockIdx.x;   // heavy tiles first
    const int bh   = blockIdx.y;
    const int b    = bh >> 4;
    const int h    = bh & 15;
    const int q0   = qt * 64;

    const int a_row = (lane & 7) + 8 * ((lane >> 3) & 1);
    const int a_col = 4 * (lane >> 4);
    const int b_row = 8 * (lane >> 4) + (lane & 7);
    const int b_col = 4 * ((lane >> 3) & 1);

    const size_t base = ((size_t)b * SEQ) * DMODEL + (size_t)h * HDIM;

    auto load_tile = [&](uint32_t* dst, const float* src, int r0) {
        uint32_t db = sm_u32(dst);
        #pragma unroll
        for (int i = 0; i < 8; i++) {
            int gi = tid + i * 128;
            int r = gi >> 4, c = gi & 15;
            cp16(db + (r * ASTR + c * 4) * 4, src + base + (size_t)(r0 + r) * DMODEL + c * 4);
        }
    };

    // prologue: group1 = Q + K0, group2 = V0
    load_tile(Qs, Q, q0);
    load_tile(Ks, K, 0);
    cp_commit();
    load_tile(Vs, V, 0);
    cp_commit();

    const uint32_t aQ = sm_u32(Qs + (w * 16 + a_row) * ASTR + a_col);
    const uint32_t aP = sm_u32(Ps + (w * 16 + a_row) * ASTR + a_col);
    const uint32_t aK = sm_u32(Ks + b_row * ASTR + b_col);

    float o[8][4];
    #pragma unroll
    for (int nf = 0; nf < 8; nf++)
        #pragma unroll
        for (int j = 0; j < 4; j++) o[nf][j] = 0.0f;
    float mi0 = -1e30f, mi1 = -1e30f, li0 = 0.0f, li1 = 0.0f;

    for (int kt = 0; kt <= qt; kt++) {
        // K(kt) ready: everything except the most recent group is complete.
        cp_wait<1>();
        __syncthreads();

        // ---- S = Q @ K^T ----
        float s[8][4];
        #pragma unroll
        for (int nf = 0; nf < 8; nf++)
            #pragma unroll
            for (int j = 0; j < 4; j++) s[nf][j] = 0.0f;

        #pragma unroll
        for (int kk = 0; kk < 8; kk++) {
            uint32_t af[4];
            ldsm4(aQ + kk * 32, af[0], af[1], af[2], af[3]);
            #pragma unroll
            for (int p = 0; p < 4; p++) {
                uint32_t b0, b1, b2, b3;
                ldsm4(aK + (p * 16 * ASTR) * 4 + kk * 32, b0, b1, b2, b3);
                uint32_t bf0[2] = {b0, b1};
                uint32_t bf1[2] = {b2, b3};
                mma_tf32(s[2*p],     af, bf0);
                mma_tf32(s[2*p + 1], af, bf1);
            }
        }

        // All warps finished reading Ks -> safe to overwrite with K(kt+1)
        __syncthreads();
        if (kt < qt) {
            load_tile(Ks, K, (kt + 1) * 64);
            cp_commit();
        }

        // ---- causal mask on the diagonal tile ----
        if (kt == qt) {
            int row0 = q0 + w * 16 + g;
            int row1 = row0 + 8;
            int k0 = kt * 64;
            #pragma unroll
            for (int nf = 0; nf < 8; nf++) {
                int c0 = k0 + nf * 8 + 2 * q;
                if (c0 > row0)     s[nf][0] = -1e30f;
                if (c0 + 1 > row0) s[nf][1] = -1e30f;
                if (c0 > row1)     s[nf][2] = -1e30f;
                if (c0 + 1 > row1) s[nf][3] = -1e30f;
            }
        }

        // ---- online softmax ----
        float mx0 = -1e30f, mx1 = -1e30f;
        #pragma unroll
        for (int nf = 0; nf < 8; nf++) {
            mx0 = fmaxf(mx0, fmaxf(s[nf][0], s[nf][1]));
            mx1 = fmaxf(mx1, fmaxf(s[nf][2], s[nf][3]));
        }
        mx0 = fmaxf(mx0, __shfl_xor_sync(0xffffffffu, mx0, 1));
        mx0 = fmaxf(mx0, __shfl_xor_sync(0xffffffffu, mx0, 2));
        mx1 = fmaxf(mx1, __shfl_xor_sync(0xffffffffu, mx1, 1));
        mx1 = fmaxf(mx1, __shfl_xor_sync(0xffffffffu, mx1, 2));
        float mn0 = fmaxf(mi0, mx0);
        float mn1 = fmaxf(mi1, mx1);

        float rs0 = 0.0f, rs1 = 0.0f;
        #pragma unroll
        for (int nf = 0; nf < 8; nf++) {
            s[nf][0] = __expf(s[nf][0] - mn0);
            s[nf][1] = __expf(s[nf][1] - mn0);
            s[nf][2] = __expf(s[nf][2] - mn1);
            s[nf][3] = __expf(s[nf][3] - mn1);
            rs0 += s[nf][0] + s[nf][1];
            rs1 += s[nf][2] + s[nf][3];
        }
        rs0 += __shfl_xor_sync(0xffffffffu, rs0, 1);
        rs0 += __shfl_xor_sync(0xffffffffu, rs0, 2);
        rs1 += __shfl_xor_sync(0xffffffffu, rs1, 1);
        rs1 += __shfl_xor_sync(0xffffffffu, rs1, 2);

        float al0 = __expf(mi0 - mn0);
        float al1 = __expf(mi1 - mn1);
        li0 = li0 * al0 + rs0;
        li1 = li1 * al1 + rs1;
        mi0 = mn0;
        mi1 = mn1;
        #pragma unroll
        for (int nf = 0; nf < 8; nf++) {
            o[nf][0] *= al0;
            o[nf][1] *= al0;
            o[nf][2] *= al1;
            o[nf][3] *= al1;
        }

        // ---- P -> smem (tf32), per-warp private 16 rows ----
        #pragma unroll
        for (int nf = 0; nf < 8; nf++) {
            int r0 = w * 16 + g;
            int cc = nf * 8 + 2 * q;
            Ps[r0 * ASTR + cc]           = f2tf(s[nf][0]);
            Ps[r0 * ASTR + cc + 1]       = f2tf(s[nf][1]);
            Ps[(r0 + 8) * ASTR + cc]     = f2tf(s[nf][2]);
            Ps[(r0 + 8) * ASTR + cc + 1] = f2tf(s[nf][3]);
        }
        __syncwarp();

        // V(kt) ready. If K(kt+1) was committed after V(kt), allow it to
        // remain outstanding; otherwise (last iter) drain everything.
        if (kt < qt) cp_wait<1>(); else cp_wait<0>();
        __syncthreads();

        // ---- O += P @ V ----
        const uint32_t* vb = Vs + q * ASTR + g;
        #pragma unroll
        for (int ks = 0; ks < 8; ks++) {
            uint32_t af[4];
            ldsm4(aP + ks * 32, af[0], af[1], af[2], af[3]);
            const uint32_t* vk = vb + ks * 8 * ASTR;
            #pragma unroll
            for (int p = 0; p < 4; p++) {
                uint32_t bf0[2] = { vk[16 * p],     vk[4 * ASTR + 16 * p] };
                uint32_t bf1[2] = { vk[16 * p + 8], vk[4 * ASTR + 16 * p + 8] };
                mma_tf32(o[2*p],     af, bf0);
                mma_tf32(o[2*p + 1], af, bf1);
            }
        }

        // All warps finished reading Vs -> safe to overwrite with V(kt+1)
        if (kt < qt) {
            __syncthreads();
            load_tile(Vs, V, (kt + 1) * 64);
            cp_commit();
        }
    }

    // ---- epilogue: normalize, round to tf32 (input of O-proj), store ----
    float inv0 = 1.0f / li0;
    float inv1 = 1.0f / li1;
    int row0 = q0 + w * 16 + g;
    #pragma unroll
    for (int nf = 0; nf < 8; nf++) {
        int col = nf * 8 + 2 * q;
        float2 v0 = make_float2(__uint_as_float(f2tf(o[nf][0] * inv0)),
                                __uint_as_float(f2tf(o[nf][1] * inv0)));
        float2 v1 = make_float2(__uint_as_float(f2tf(o[nf][2] * inv1)),
                                __uint_as_float(f2tf(o[nf][3] * inv1)));
        *(float2*)(Cx + base + (size_t)row0 * DMODEL + col) = v0;
        *(float2*)(Cx + base + (size_t)(row0 + 8) * DMODEL + col) = v1;
    }
}

// ---------------------------------------------------------------------------
extern "C" void kernel_launch(void* const* d_in, const int* in_sizes, int n_in,
                              void* d_out, int out_size)
{
    const float* query = (const float*)d_in[0];
    const float* key   = (const float*)d_in[1];
    const float* value = (const float*)d_in[2];
    // d_in[3] = mask: constant causal tril; handled analytically.
    const float* wq = (const float*)d_in[4];
    const float* bq = (const float*)d_in[5];
    const float* wk = (const float*)d_in[6];
    const float* bk = (const float*)d_in[7];
    const float* wv = (const float*)d_in[8];
    const float* bv = (const float*)d_in[9];
    const float* wo = (const float*)d_in[10];
    const float* bo = (const float*)d_in[11];
    float* out = (float*)d_out;

    float *Q, *K, *V, *C, *T, *Wr;
    cudaGetSymbolAddress((void**)&Q,  g_Q);
    cudaGetSymbolAddress((void**)&K,  g_K);
    cudaGetSymbolAddress((void**)&V,  g_V);
    cudaGetSymbolAddress((void**)&C,  g_C);
    cudaGetSymbolAddress((void**)&T,  g_T);
    cudaGetSymbolAddress((void**)&Wr, g_Wr);
    const size_t NA = (size_t)MROWS * DMODEL;
    const size_t NW = (size_t)DMODEL * DMODEL;
    float* T0 = T;          float* T1 = T + NA;      float* T2 = T + 2 * NA;
    float* W0 = Wr;         float* W1 = Wr + NW;
    float* W2 = Wr + 2*NW;  float* W3 = Wr + 3 * NW;

    cudaFuncSetAttribute(gemm_mma,
                         cudaFuncAttributeMaxDynamicSharedMemorySize, GEMM_SMEM);
    cudaFuncSetAttribute(gemm_qkv,
                         cudaFuncAttributeMaxDynamicSharedMemorySize, GEMM_SMEM);
    cudaFuncSetAttribute(attn_mma,
                         cudaFuncAttributeMaxDynamicSharedMemorySize, ATTN_SMEM);

    const int nact4 = (int)(NA / 4);   // 2,097,152
    const int nw4   = (int)(NW / 4);   // 262,144

    // Batched rounding
    Round3Args ra = {query, key, value, T0, T1, T2};
    round3_kernel<<<dim3((nact4 + 255) / 256, 3), 256>>>(ra, nact4);
    Round4Args rw = {wq, wk, wv, wo, W0, W1, W2, W3};
    round4_kernel<<<dim3((nw4 + 255) / 256, 4), 256>>>(rw, nw4);

    // Fused Q/K/V projections (Q output pre-scaled by 1/8, all tf32-rounded)
    QKVArgs qa = {T0, T1, T2, W0, W1, W2, bq, bk, bv, Q, K, V};
    dim3 gridQKV(DMODEL / 128, MROWS / 128, 3);   // (8, 64, 3)
    gemm_qkv<<<gridQKV, 256, GEMM_SMEM>>>(qa);

    // Attention (writes tf32-rounded C)
    dim3 gridA(SEQ / 64, BATCH * NHEAD);          // (32, 64)
    attn_mma<<<gridA, 128, ATTN_SMEM>>>(Q, K, V, C);

    // Output projection (plain fp32 output)
    dim3 gridG(DMODEL / 128, MROWS / 128);        // (8, 64)
    gemm_mma<<<gridG, 256, GEMM_SMEM>>>(C, W3, bo, out, 0, 1.0f);
}

// round 10
// speedup vs baseline: 2.0043x; 1.0986x over previous
#include <cuda_runtime.h>
#include <cstdint>
#include <math.h>

// Problem constants
#define BATCH 4
#define SEQ   2048
#define DMODEL 1024
#define NHEAD 16
#define HDIM  64
#define MROWS (BATCH * SEQ)   // 8192

// Scratch (allocation-free rule: __device__ globals)
__device__ float g_Q[(size_t)MROWS * DMODEL];
__device__ float g_K[(size_t)MROWS * DMODEL];
__device__ float g_V[(size_t)MROWS * DMODEL];
__device__ float g_C[(size_t)MROWS * DMODEL];
__device__ float g_T[3][(size_t)MROWS * DMODEL];   // tf32-rounded activations
__device__ float g_Wr[4][(size_t)DMODEL * DMODEL]; // tf32-rounded weights

// ---------------------------------------------------------------------------
// Helpers
// ---------------------------------------------------------------------------
__device__ __forceinline__ uint32_t f2tf(float x) {
    uint32_t r;
    asm("cvt.rna.tf32.f32 %0, %1;" : "=r"(r) : "f"(x));
    return r;
}
__device__ __forceinline__ void mma_tf32(float* c, const uint32_t* a, const uint32_t* b) {
    asm volatile(
        "mma.sync.aligned.m16n8k8.row.col.f32.tf32.tf32.f32 "
        "{%0,%1,%2,%3}, {%4,%5,%6,%7}, {%8,%9}, {%0,%1,%2,%3};"
        : "+f"(c[0]), "+f"(c[1]), "+f"(c[2]), "+f"(c[3])
        : "r"(a[0]), "r"(a[1]), "r"(a[2]), "r"(a[3]), "r"(b[0]), "r"(b[1]));
}
__device__ __forceinline__ uint32_t sm_u32(const void* p) {
    return (uint32_t)__cvta_generic_to_shared(p);
}
__device__ __forceinline__ void ldsm4(uint32_t addr, uint32_t& r0, uint32_t& r1,
                                      uint32_t& r2, uint32_t& r3) {
    asm volatile("ldmatrix.sync.aligned.m8n8.x4.shared.b16 {%0,%1,%2,%3}, [%4];"
                 : "=r"(r0), "=r"(r1), "=r"(r2), "=r"(r3) : "r"(addr));
}
__device__ __forceinline__ void cp16(uint32_t saddr, const void* gaddr) {
    asm volatile("cp.async.cg.shared.global [%0], [%1], 16;"
                 :: "r"(saddr), "l"(gaddr));
}
__device__ __forceinline__ void cp_commit() {
    asm volatile("cp.async.commit_group;" ::: "memory");
}
template <int N>
__device__ __forceinline__ void cp_wait() {
    asm volatile("cp.async.wait_group %0;" :: "n"(N) : "memory");
}

// ---------------------------------------------------------------------------
// Batched tf32 rounding (round-to-nearest).
// ---------------------------------------------------------------------------
struct Round3Args { const float *i0, *i1, *i2; float *o0, *o1, *o2; };
__global__ void round3_kernel(Round3Args a, int n4)
{
    int i = blockIdx.x * blockDim.x + threadIdx.x;
    if (i >= n4) return;
    const float* in = (blockIdx.y == 0) ? a.i0 : (blockIdx.y == 1) ? a.i1 : a.i2;
    float* out      = (blockIdx.y == 0) ? a.o0 : (blockIdx.y == 1) ? a.o1 : a.o2;
    float4 v = ((const float4*)in)[i];
    float4 o;
    o.x = __uint_as_float(f2tf(v.x));
    o.y = __uint_as_float(f2tf(v.y));
    o.z = __uint_as_float(f2tf(v.z));
    o.w = __uint_as_float(f2tf(v.w));
    ((float4*)out)[i] = o;
}
struct Round4Args { const float *i0, *i1, *i2, *i3; float *o0, *o1, *o2, *o3; };
__global__ void round4_kernel(Round4Args a, int n4)
{
    int i = blockIdx.x * blockDim.x + threadIdx.x;
    if (i >= n4) return;
    const float* in;
    float* out;
    switch (blockIdx.y) {
        case 0: in = a.i0; out = a.o0; break;
        case 1: in = a.i1; out = a.o1; break;
        case 2: in = a.i2; out = a.o2; break;
        default: in = a.i3; out = a.o3; break;
    }
    float4 v = ((const float4*)in)[i];
    float4 o;
    o.x = __uint_as_float(f2tf(v.x));
    o.y = __uint_as_float(f2tf(v.y));
    o.z = __uint_as_float(f2tf(v.z));
    o.w = __uint_as_float(f2tf(v.w));
    ((float4*)out)[i] = o;
}

// ---------------------------------------------------------------------------
// GEMM core: C[M,N] = A[M,K] @ W[N,K]^T + bias[N], tf32 mma.sync.
// Pre-rounded inputs. 3-stage cp.async pipeline, ldmatrix consumers.
// CTA tile 128x128, BK=32, 8 warps. block = 256.
// mode != 0: out = rna_tf32((acc + bias) * oscale); else plain fp32.
// ---------------------------------------------------------------------------
#define GSTR 36
#define GTILE (128 * GSTR)
#define GSTAGE (2 * GTILE)
#define GEMM_SMEM (3 * GSTAGE * 4)   // 110,592 B

__device__ __forceinline__ void gemm_body(
    const float* __restrict__ A, const float* __restrict__ W,
    const float* __restrict__ bias, float* __restrict__ C,
    int mode, float oscale, uint32_t* smg, int m0, int n0)
{
    const int tid  = threadIdx.x;
    const int lane = tid & 31;
    const int wid  = tid >> 5;
    const int wm   = wid & 3;
    const int wn   = wid >> 2;
    const int g    = lane >> 2;
    const int q    = lane & 3;

    const int a_row = (lane & 7) + 8 * ((lane >> 3) & 1);
    const int a_col = 4 * (lane >> 4);
    const int b_row = 8 * (lane >> 4) + (lane & 7);
    const int b_col = 4 * ((lane >> 3) & 1);

    float acc[2][8][4];
    #pragma unroll
    for (int mf = 0; mf < 2; mf++)
        #pragma unroll
        for (int nf = 0; nf < 8; nf++)
            #pragma unroll
            for (int j = 0; j < 4; j++) acc[mf][nf][j] = 0.0f;

    const uint32_t sbase = sm_u32(smg);
    auto load_stage = [&](int stage, int kc) {
        uint32_t ab = sbase + stage * (GSTAGE * 4);
        uint32_t wb = ab + GTILE * 4;
        #pragma unroll
        for (int i = 0; i < 4; i++) {
            int gi = tid + i * 256;
            int r = gi >> 3, c = gi & 7;
            cp16(ab + (r * GSTR + c * 4) * 4, A + (size_t)(m0 + r) * DMODEL + kc + c * 4);
            cp16(wb + (r * GSTR + c * 4) * 4, W + (size_t)(n0 + r) * DMODEL + kc + c * 4);
        }
        cp_commit();
    };

    load_stage(0, 0);
    load_stage(1, 32);

    const int NCHUNK = DMODEL / 32;
    for (int c = 0; c < NCHUNK; c++) {
        cp_wait<1>();
        __syncthreads();
        if (c + 2 < NCHUNK)
            load_stage((c + 2) % 3, (c + 2) * 32);

        const uint32_t* Sb = smg + (c % 3) * GSTAGE;
        const uint32_t aA0 = sm_u32(Sb + (wm * 32 + a_row) * GSTR + a_col);
        const uint32_t aA1 = aA0 + 16 * GSTR * 4;
        const uint32_t aB  = sm_u32(Sb + GTILE + (wn * 64 + b_row) * GSTR + b_col);

        #pragma unroll
        for (int kk = 0; kk < 4; kk++) {
            uint32_t af0[4], af1[4];
            ldsm4(aA0 + kk * 32, af0[0], af0[1], af0[2], af0[3]);
            ldsm4(aA1 + kk * 32, af1[0], af1[1], af1[2], af1[3]);
            #pragma unroll
            for (int p = 0; p < 4; p++) {
                uint32_t b0, b1, b2, b3;
                ldsm4(aB + (p * 16 * GSTR) * 4 + kk * 32, b0, b1, b2, b3);
                uint32_t bf0[2] = {b0, b1};
                uint32_t bf1[2] = {b2, b3};
                mma_tf32(acc[0][2*p],     af0, bf0);
                mma_tf32(acc[1][2*p],     af1, bf0);
                mma_tf32(acc[0][2*p + 1], af0, bf1);
                mma_tf32(acc[1][2*p + 1], af1, bf1);
            }
        }
        __syncthreads();
    }

    #pragma unroll
    for (int mf = 0; mf < 2; mf++) {
        int row0 = m0 + wm * 32 + mf * 16 + g;
        #pragma unroll
        for (int nf = 0; nf < 8; nf++) {
            int col = n0 + wn * 64 + nf * 8 + 2 * q;
            float b0 = __ldg(bias + col);
            float b1 = __ldg(bias + col + 1);
            float v00 = acc[mf][nf][0] + b0, v01 = acc[mf][nf][1] + b1;
            float v10 = acc[mf][nf][2] + b0, v11 = acc[mf][nf][3] + b1;
            if (mode) {
                v00 = __uint_as_float(f2tf(v00 * oscale));
                v01 = __uint_as_float(f2tf(v01 * oscale));
                v10 = __uint_as_float(f2tf(v10 * oscale));
                v11 = __uint_as_float(f2tf(v11 * oscale));
            }
            *(float2*)(C + (size_t)row0 * DMODEL + col) = make_float2(v00, v01);
            *(float2*)(C + (size_t)(row0 + 8) * DMODEL + col) = make_float2(v10, v11);
        }
    }
}

// Single GEMM (output projection)
__global__ __launch_bounds__(256, 2) void gemm_mma(
    const float* __restrict__ A, const float* __restrict__ W,
    const float* __restrict__ bias, float* __restrict__ C,
    int mode, float oscale)
{
    extern __shared__ __align__(16) uint32_t smg[];
    gemm_body(A, W, bias, C, mode, oscale, smg, blockIdx.y * 128, blockIdx.x * 128);
}

// Fused Q/K/V projections: blockIdx.z selects stream (z=0 Q with 0.125 scale).
struct QKVArgs {
    const float *A0, *A1, *A2;
    const float *W0, *W1, *W2;
    const float *b0, *b1, *b2;
    float *O0, *O1, *O2;
};
__global__ __launch_bounds__(256, 2) void gemm_qkv(QKVArgs a)
{
    extern __shared__ __align__(16) uint32_t smg[];
    const int z = blockIdx.z;
    const float* A = (z == 0) ? a.A0 : (z == 1) ? a.A1 : a.A2;
    const float* W = (z == 0) ? a.W0 : (z == 1) ? a.W1 : a.W2;
    const float* b = (z == 0) ? a.b0 : (z == 1) ? a.b1 : a.b2;
    float* O       = (z == 0) ? a.O0 : (z == 1) ? a.O1 : a.O2;
    float oscale   = (z == 0) ? 0.125f : 1.0f;
    gemm_body(A, W, b, O, 1, oscale, smg, blockIdx.y * 128, blockIdx.x * 128);
}

// ---------------------------------------------------------------------------
// Causal flash attention via tf32 mma.sync. Br = Bc = 64, 4 warps.
// Q/K/V pre-rounded (Q pre-scaled by 1/8). Single-buffered K and V with
// cp.async group-order pipelining. Q fragments hoisted to registers.
// V stride 72 (bank-conflict-free scalar B loads); P stores as STS.64.
// smem: Q,K,P @ stride 68 + V @ stride 72 = 70,656 B -> 3 CTAs/SM.
// grid = (32, 64) heavy-first, block = 128.
// ---------------------------------------------------------------------------
#define ASTR 68
#define VSTR 72
#define ATILE (64 * ASTR)
#define VTILE (64 * VSTR)
#define ATTN_SMEM ((3 * ATILE + VTILE) * 4)   // 70,656 B

__global__ __launch_bounds__(128) void attn_mma(
    const float* __restrict__ Q,
    const float* __restrict__ K,
    const float* __restrict__ V,
    float* __restrict__ Cx)
{
    extern __shared__ __align__(16) uint32_t sma[];
    uint32_t* Qs = sma;                // [qrow][dk]   stride 68
    uint32_t* Ks = sma + ATILE;        // [key][dk]    stride 68
    uint32_t* Ps = sma + 2 * ATILE;    // [qrow][key]  stride 68
    uint32_t* Vs = sma + 3 * ATILE;    // [key][dk]    stride 72

    const int tid  = threadIdx.x;
    const int lane = tid & 31;
    const int w    = tid >> 5;
    const int g    = lane >> 2;
    const int q    = lane & 3;
    const int qt   = gridDim.x - 1 - blockIdx.x;   // heavy tiles first
    const int bh   = blockIdx.y;
    const int b    = bh >> 4;
    const int h    = bh & 15;
    const int q0   = qt * 64;

    const int a_row = (lane & 7) + 8 * ((lane >> 3) & 1);
    const int a_col = 4 * (lane >> 4);
    const int b_row = 8 * (lane >> 4) + (lane & 7);
    const int b_col = 4 * ((lane >> 3) & 1);

    const size_t base = ((size_t)b * SEQ) * DMODEL + (size_t)h * HDIM;

    auto load_tile = [&](uint32_t* dst, const float* src, int r0, int stride) {
        uint32_t db = sm_u32(dst);
        #pragma unroll
        for (int i = 0; i < 8; i++) {
            int gi = tid + i * 128;
            int r = gi >> 4, c = gi & 15;
            cp16(db + (r * stride + c * 4) * 4, src + base + (size_t)(r0 + r) * DMODEL + c * 4);
        }
    };

    // prologue: group A = Q + K0, group B = V0
    load_tile(Qs, Q, q0, ASTR);
    load_tile(Ks, K, 0, ASTR);
    cp_commit();
    load_tile(Vs, V, 0, VSTR);
    cp_commit();

    const uint32_t aQ = sm_u32(Qs + (w * 16 + a_row) * ASTR + a_col);
    const uint32_t aP = sm_u32(Ps + (w * 16 + a_row) * ASTR + a_col);
    const uint32_t aK = sm_u32(Ks + b_row * ASTR + b_col);

    // Q fragments: loop-invariant, hoisted to registers (Q ready after wait<1>)
    cp_wait<1>();
    __syncthreads();
    uint32_t qf[8][4];
    #pragma unroll
    for (int kk = 0; kk < 8; kk++)
        ldsm4(aQ + kk * 32, qf[kk][0], qf[kk][1], qf[kk][2], qf[kk][3]);

    float o[8][4];
    #pragma unroll
    for (int nf = 0; nf < 8; nf++)
        #pragma unroll
        for (int j = 0; j < 4; j++) o[nf][j] = 0.0f;
    float mi0 = -1e30f, mi1 = -1e30f, li0 = 0.0f, li1 = 0.0f;

    for (int kt = 0; kt <= qt; kt++) {
        // K(kt) ready: everything except the most recent group is complete.
        cp_wait<1>();
        __syncthreads();

        // ---- S = Q @ K^T ----
        float s[8][4];
        #pragma unroll
        for (int nf = 0; nf < 8; nf++)
            #pragma unroll
            for (int j = 0; j < 4; j++) s[nf][j] = 0.0f;

        #pragma unroll
        for (int kk = 0; kk < 8; kk++) {
            #pragma unroll
            for (int p = 0; p < 4; p++) {
                uint32_t b0, b1, b2, b3;
                ldsm4(aK + (p * 16 * ASTR) * 4 + kk * 32, b0, b1, b2, b3);
                uint32_t bf0[2] = {b0, b1};
                uint32_t bf1[2] = {b2, b3};
                mma_tf32(s[2*p],     qf[kk], bf0);
                mma_tf32(s[2*p + 1], qf[kk], bf1);
            }
        }

        // All warps finished reading Ks -> safe to overwrite with K(kt+1)
        __syncthreads();
        if (kt < qt) {
            load_tile(Ks, K, (kt + 1) * 64, ASTR);
            cp_commit();
        }

        // ---- causal mask on the diagonal tile ----
        if (kt == qt) {
            int row0 = q0 + w * 16 + g;
            int row1 = row0 + 8;
            int k0 = kt * 64;
            #pragma unroll
            for (int nf = 0; nf < 8; nf++) {
                int c0 = k0 + nf * 8 + 2 * q;
                if (c0 > row0)     s[nf][0] = -1e30f;
                if (c0 + 1 > row0) s[nf][1] = -1e30f;
                if (c0 > row1)     s[nf][2] = -1e30f;
                if (c0 + 1 > row1) s[nf][3] = -1e30f;
            }
        }

        // ---- online softmax ----
        float mx0 = -1e30f, mx1 = -1e30f;
        #pragma unroll
        for (int nf = 0; nf < 8; nf++) {
            mx0 = fmaxf(mx0, fmaxf(s[nf][0], s[nf][1]));
            mx1 = fmaxf(mx1, fmaxf(s[nf][2], s[nf][3]));
        }
        mx0 = fmaxf(mx0, __shfl_xor_sync(0xffffffffu, mx0, 1));
        mx0 = fmaxf(mx0, __shfl_xor_sync(0xffffffffu, mx0, 2));
        mx1 = fmaxf(mx1, __shfl_xor_sync(0xffffffffu, mx1, 1));
        mx1 = fmaxf(mx1, __shfl_xor_sync(0xffffffffu, mx1, 2));
        float mn0 = fmaxf(mi0, mx0);
        float mn1 = fmaxf(mi1, mx1);

        float rs0 = 0.0f, rs1 = 0.0f;
        #pragma unroll
        for (int nf = 0; nf < 8; nf++) {
            s[nf][0] = __expf(s[nf][0] - mn0);
            s[nf][1] = __expf(s[nf][1] - mn0);
            s[nf][2] = __expf(s[nf][2] - mn1);
            s[nf][3] = __expf(s[nf][3] - mn1);
            rs0 += s[nf][0] + s[nf][1];
            rs1 += s[nf][2] + s[nf][3];
        }
        rs0 += __shfl_xor_sync(0xffffffffu, rs0, 1);
        rs0 += __shfl_xor_sync(0xffffffffu, rs0, 2);
        rs1 += __shfl_xor_sync(0xffffffffu, rs1, 1);
        rs1 += __shfl_xor_sync(0xffffffffu, rs1, 2);

        float al0 = __expf(mi0 - mn0);
        float al1 = __expf(mi1 - mn1);
        li0 = li0 * al0 + rs0;
        li1 = li1 * al1 + rs1;
        mi0 = mn0;
        mi1 = mn1;
        #pragma unroll
        for (int nf = 0; nf < 8; nf++) {
            o[nf][0] *= al0;
            o[nf][1] *= al0;
            o[nf][2] *= al1;
            o[nf][3] *= al1;
        }

        // ---- P -> smem (tf32), per-warp private 16 rows, STS.64 ----
        #pragma unroll
        for (int nf = 0; nf < 8; nf++) {
            int r0 = w * 16 + g;
            int cc = nf * 8 + 2 * q;
            *(uint2*)&Ps[r0 * ASTR + cc]       = make_uint2(f2tf(s[nf][0]), f2tf(s[nf][1]));
            *(uint2*)&Ps[(r0 + 8) * ASTR + cc] = make_uint2(f2tf(s[nf][2]), f2tf(s[nf][3]));
        }
        __syncwarp();

        // V(kt) ready (all but the newest group; last iter: drain all).
        if (kt < qt) cp_wait<1>(); else cp_wait<0>();
        __syncthreads();

        // ---- O += P @ V (V stride 72: conflict-free scalar B loads) ----
        const uint32_t* vb = Vs + q * VSTR + g;
        #pragma unroll
        for (int ks = 0; ks < 8; ks++) {
            uint32_t af[4];
            ldsm4(aP + ks * 32, af[0], af[1], af[2], af[3]);
            const uint32_t* vk = vb + ks * 8 * VSTR;
            #pragma unroll
            for (int p = 0; p < 4; p++) {
                uint32_t bf0[2] = { vk[16 * p],     vk[4 * VSTR + 16 * p] };
                uint32_t bf1[2] = { vk[16 * p + 8], vk[4 * VSTR + 16 * p + 8] };
                mma_tf32(o[2*p],     af, bf0);
                mma_tf32(o[2*p + 1], af, bf1);
            }
        }

        // All warps finished reading Vs -> safe to overwrite with V(kt+1)
        if (kt < qt) {
            __syncthreads();
            load_tile(Vs, V, (kt + 1) * 64, VSTR);
            cp_commit();
        }
    }

    // ---- epilogue: normalize, round to tf32 (input of O-proj), store ----
    float inv0 = 1.0f / li0;
    float inv1 = 1.0f / li1;
    int row0 = q0 + w * 16 + g;
    #pragma unroll
    for (int nf = 0; nf < 8; nf++) {
        int col = nf * 8 + 2 * q;
        float2 v0 = make_float2(__uint_as_float(f2tf(o[nf][0] * inv0)),
                                __uint_as_float(f2tf(o[nf][1] * inv0)));
        float2 v1 = make_float2(__uint_as_float(f2tf(o[nf][2] * inv1)),
                                __uint_as_float(f2tf(o[nf][3] * inv1)));
        *(float2*)(Cx + base + (size_t)row0 * DMODEL + col) = v0;
        *(float2*)(Cx + base + (size_t)(row0 + 8) * DMODEL + col) = v1;
    }
}

// ---------------------------------------------------------------------------
extern "C" void kernel_launch(void* const* d_in, const int* in_sizes, int n_in,
                              void* d_out, int out_size)
{
    const float* query = (const float*)d_in[0];
    const float* key   = (const float*)d_in[1];
    const float* value = (const float*)d_in[2];
    // d_in[3] = mask: constant causal tril; handled analytically.
    const float* wq = (const float*)d_in[4];
    const float* bq = (const float*)d_in[5];
    const float* wk = (const float*)d_in[6];
    const float* bk = (const float*)d_in[7];
    const float* wv = (const float*)d_in[8];
    const float* bv = (const float*)d_in[9];
    const float* wo = (const float*)d_in[10];
    const float* bo = (const float*)d_in[11];
    float* out = (float*)d_out;

    float *Q, *K, *V, *C, *T, *Wr;
    cudaGetSymbolAddress((void**)&Q,  g_Q);
    cudaGetSymbolAddress((void**)&K,  g_K);
    cudaGetSymbolAddress((void**)&V,  g_V);
    cudaGetSymbolAddress((void**)&C,  g_C);
    cudaGetSymbolAddress((void**)&T,  g_T);
    cudaGetSymbolAddress((void**)&Wr, g_Wr);
    const size_t NA = (size_t)MROWS * DMODEL;
    const size_t NW = (size_t)DMODEL * DMODEL;
    float* T0 = T;          float* T1 = T + NA;      float* T2 = T + 2 * NA;
    float* W0 = Wr;         float* W1 = Wr + NW;
    float* W2 = Wr + 2*NW;  float* W3 = Wr + 3 * NW;

    cudaFuncSetAttribute(gemm_mma,
                         cudaFuncAttributeMaxDynamicSharedMemorySize, GEMM_SMEM);
    cudaFuncSetAttribute(gemm_qkv,
                         cudaFuncAttributeMaxDynamicSharedMemorySize, GEMM_SMEM);
    cudaFuncSetAttribute(attn_mma,
                         cudaFuncAttributeMaxDynamicSharedMemorySize, ATTN_SMEM);

    const int nact4 = (int)(NA / 4);   // 2,097,152
    const int nw4   = (int)(NW / 4);   // 262,144

    // Batched rounding
    Round3Args ra = {query, key, value, T0, T1, T2};
    round3_kernel<<<dim3((nact4 + 255) / 256, 3), 256>>>(ra, nact4);
    Round4Args rw = {wq, wk, wv, wo, W0, W1, W2, W3};
    round4_kernel<<<dim3((nw4 + 255) / 256, 4), 256>>>(rw, nw4);

    // Fused Q/K/V projections (Q output pre-scaled by 1/8, all tf32-rounded)
    QKVArgs qa = {T0, T1, T2, W0, W1, W2, bq, bk, bv, Q, K, V};
    dim3 gridQKV(DMODEL / 128, MROWS / 128, 3);   // (8, 64, 3)
    gemm_qkv<<<gridQKV, 256, GEMM_SMEM>>>(qa);

    // Attention (writes tf32-rounded C)
    dim3 gridA(SEQ / 64, BATCH * NHEAD);          // (32, 64)
    attn_mma<<<gridA, 128, ATTN_SMEM>>>(Q, K, V, C);

    // Output projection (plain fp32 output)
    dim3 gridG(DMODEL / 128, MROWS / 128);        // (8, 64)
    gemm_mma<<<gridG, 256, GEMM_SMEM>>>(C, W3, bo, out, 0, 1.0f);
}